// round 1
// baseline (speedup 1.0000x reference)
#include <cuda_runtime.h>
#include <math.h>

// Problem dims (fixed by the dataset)
#define Bc 256
#define Nc 4096
#define Mc 16384
#define STEPS 50

// Scratch (no allocations allowed -> __device__ globals)
__device__ float g_h[(size_t)Bc * Mc];   // 16 MB: h, then f in-place
__device__ float g_norm[STEPS];
__device__ int   g_done;

// ---------------------------------------------------------------------------
// Init: state <- input (state lives directly in d_out), reset flags/norms
// ---------------------------------------------------------------------------
__global__ void k_init(const float* __restrict__ inp, float* __restrict__ state) {
    int i = blockIdx.x * blockDim.x + threadIdx.x;
    if (i < Bc * Nc) state[i] = inp[i];
    if (i < STEPS) g_norm[i] = 0.0f;
    if (i == 0) g_done = 0;
}

// ---------------------------------------------------------------------------
// GEMM1: h[b,m] = sum_n W[m,n] * state[b,n]
// C tile: 128 (m) x 64 (b), K tile 16, 256 threads, 8x4 per thread
// ---------------------------------------------------------------------------
__global__ void __launch_bounds__(256) k_gemm1(const float* __restrict__ W,
                                               const float* __restrict__ state) {
    if (g_done) return;   // frozen: skip all work

    __shared__ float As[16][128 + 4];   // W   staged as [k][m]
    __shared__ float Bs[16][64 + 4];    // s   staged as [k][b]

    const int m0 = blockIdx.x * 128;
    const int b0 = blockIdx.y * 64;
    const int tid = threadIdx.x;
    const int tx = tid & 15;            // 0..15 -> b
    const int ty = tid >> 4;            // 0..15 -> m

    float acc[8][4];
#pragma unroll
    for (int i = 0; i < 8; i++)
#pragma unroll
        for (int j = 0; j < 4; j++) acc[i][j] = 0.0f;

    for (int k0 = 0; k0 < Nc; k0 += 16) {
        // W tile: 128x16 = 512 float4 loads (2 per thread), transpose into As
#pragma unroll
        for (int l = 0; l < 2; l++) {
            int idx = tid + l * 256;        // 0..511
            int row = idx >> 2;             // 0..127
            int kq  = (idx & 3) * 4;        // 0,4,8,12
            float4 v = *(const float4*)&W[(size_t)(m0 + row) * Nc + k0 + kq];
            As[kq + 0][row] = v.x;
            As[kq + 1][row] = v.y;
            As[kq + 2][row] = v.z;
            As[kq + 3][row] = v.w;
        }
        // state tile: 64x16 = 256 float4 loads (1 per thread), transpose into Bs
        {
            int idx  = tid;
            int brow = idx >> 2;            // 0..63
            int kq   = (idx & 3) * 4;
            float4 v = *(const float4*)&state[(size_t)(b0 + brow) * Nc + k0 + kq];
            Bs[kq + 0][brow] = v.x;
            Bs[kq + 1][brow] = v.y;
            Bs[kq + 2][brow] = v.z;
            Bs[kq + 3][brow] = v.w;
        }
        __syncthreads();

#pragma unroll
        for (int k = 0; k < 16; k++) {
            float a[8], bb[4];
#pragma unroll
            for (int i = 0; i < 8; i++) a[i] = As[k][ty * 8 + i];
#pragma unroll
            for (int j = 0; j < 4; j++) bb[j] = Bs[k][tx * 4 + j];
#pragma unroll
            for (int i = 0; i < 8; i++)
#pragma unroll
                for (int j = 0; j < 4; j++) acc[i][j] += a[i] * bb[j];
        }
        __syncthreads();
    }

    // h stored [B, M] so the softmax reads coalesced
#pragma unroll
    for (int j = 0; j < 4; j++) {
        int b = b0 + tx * 4 + j;
#pragma unroll
        for (int i = 0; i < 8; i++) {
            g_h[(size_t)b * Mc + m0 + ty * 8 + i] = acc[i][j];
        }
    }
}

// ---------------------------------------------------------------------------
// Softmax over the memory dim (M) per batch row, in place over g_h.
// beta applied inside the max pass (robust to beta < 0).
// ---------------------------------------------------------------------------
__global__ void __launch_bounds__(256) k_softmax(const float* __restrict__ beta_p) {
    if (g_done) return;

    const int b   = blockIdx.x;
    const int tid = threadIdx.x;
    const float beta = *beta_p;
    float* row = g_h + (size_t)b * Mc;

    __shared__ float red[256];

    // pass 1: max of beta*h
    float mx = -3.402823466e38f;
    for (int m = tid; m < Mc; m += 256) mx = fmaxf(mx, beta * row[m]);
    red[tid] = mx;
    __syncthreads();
    for (int s = 128; s > 0; s >>= 1) {
        if (tid < s) red[tid] = fmaxf(red[tid], red[tid + s]);
        __syncthreads();
    }
    mx = red[0];
    __syncthreads();

    // pass 2: exp + sum (write exp in place)
    float sum = 0.0f;
    for (int m = tid; m < Mc; m += 256) {
        float e = expf(beta * row[m] - mx);
        row[m] = e;
        sum += e;
    }
    red[tid] = sum;
    __syncthreads();
    for (int s = 128; s > 0; s >>= 1) {
        if (tid < s) red[tid] += red[tid + s];
        __syncthreads();
    }
    float inv = 1.0f / red[0];

    // pass 3: normalize
    for (int m = tid; m < Mc; m += 256) row[m] *= inv;
}

// ---------------------------------------------------------------------------
// GEMM2 + update fused:
//   v[b,n] = sum_m W[m,n] * f[b,m]
//   new    = s + (1/tau)*(v - s);  state <- new;  accumulate ||new - s||^2
// C tile: 64 (n) x 64 (b), K tile 16, 256 threads, 4x4 per thread
// ---------------------------------------------------------------------------
__global__ void __launch_bounds__(256) k_gemm2_update(const float* __restrict__ W,
                                                      float* __restrict__ state,
                                                      const float* __restrict__ tau_p,
                                                      int step) {
    if (g_done) return;

    __shared__ float As[16][64 + 4];   // W^T staged as [k(m)][n]
    __shared__ float Bs[16][64 + 4];   // f   staged as [k(m)][b]
    __shared__ float red[256];

    const int n0 = blockIdx.x * 64;
    const int b0 = blockIdx.y * 64;
    const int tid = threadIdx.x;
    const int tx = tid & 15;           // -> b
    const int ty = tid >> 4;           // -> n

    float acc[4][4];
#pragma unroll
    for (int i = 0; i < 4; i++)
#pragma unroll
        for (int j = 0; j < 4; j++) acc[i][j] = 0.0f;

    for (int k0 = 0; k0 < Mc; k0 += 16) {
        // W^T tile: rows m (k), cols n -> direct float4 store (no transpose)
        {
            int idx = tid;                 // 0..255
            int k   = idx >> 4;            // 0..15
            int nq  = (idx & 15) * 4;      // 0..60
            *(float4*)&As[k][nq] =
                *(const float4*)&W[(size_t)(k0 + k) * Nc + n0 + nq];
        }
        // f tile: [b][m] in gmem -> transpose into Bs[k][b]
        {
            int idx  = tid;
            int brow = idx >> 2;           // 0..63
            int kq   = (idx & 3) * 4;
            float4 v = *(const float4*)&g_h[(size_t)(b0 + brow) * Mc + k0 + kq];
            Bs[kq + 0][brow] = v.x;
            Bs[kq + 1][brow] = v.y;
            Bs[kq + 2][brow] = v.z;
            Bs[kq + 3][brow] = v.w;
        }
        __syncthreads();

#pragma unroll
        for (int k = 0; k < 16; k++) {
            float a[4], bb[4];
#pragma unroll
            for (int i = 0; i < 4; i++) a[i]  = As[k][ty * 4 + i];
#pragma unroll
            for (int j = 0; j < 4; j++) bb[j] = Bs[k][tx * 4 + j];
#pragma unroll
            for (int i = 0; i < 4; i++)
#pragma unroll
                for (int j = 0; j < 4; j++) acc[i][j] += a[i] * bb[j];
        }
        __syncthreads();
    }

    // Fused update epilogue
    const float invtau = 1.0f / (*tau_p);
    float sumsq = 0.0f;
#pragma unroll
    for (int j = 0; j < 4; j++) {
        int b = b0 + tx * 4 + j;
#pragma unroll
        for (int i = 0; i < 4; i++) {
            int n = n0 + ty * 4 + i;
            size_t idx = (size_t)b * Nc + n;
            float so = state[idx];
            float nv = so + invtau * (acc[i][j] - so);
            float d  = nv - so;
            sumsq += d * d;
            state[idx] = nv;
        }
    }

    // block-reduce sumsq, one atomic per block
    red[tid] = sumsq;
    __syncthreads();
    for (int s = 128; s > 0; s >>= 1) {
        if (tid < s) red[tid] += red[tid + s];
        __syncthreads();
    }
    if (tid == 0) atomicAdd(&g_norm[step], red[0]);
}

// ---------------------------------------------------------------------------
// Convergence latch: done |= (||delta|| <= 1e-3). Runs AFTER the step's
// update (matching the reference: the step that crosses the threshold still
// commits its update; later steps freeze).
// ---------------------------------------------------------------------------
__global__ void k_check(int step) {
    if (!g_done && sqrtf(g_norm[step]) <= 1e-3f) g_done = 1;
}

// ---------------------------------------------------------------------------
// kernel_launch: graph-capturable, allocation-free.
// Inputs (metadata order): input [B,N,1] f32, W [M,N] f32, beta f32, tau f32.
// d_out [B,N,1] f32 doubles as the state buffer.
// ---------------------------------------------------------------------------
extern "C" void kernel_launch(void* const* d_in, const int* in_sizes, int n_in,
                              void* d_out, int out_size) {
    const float* inp  = (const float*)d_in[0];
    const float* W    = (const float*)d_in[1];
    const float* beta = (const float*)d_in[2];
    const float* tau  = (const float*)d_in[3];
    float* state = (float*)d_out;

    k_init<<<(Bc * Nc + 255) / 256, 256>>>(inp, state);

    for (int s = 0; s < STEPS; s++) {
        k_gemm1<<<dim3(Mc / 128, Bc / 64), 256>>>(W, state);
        k_softmax<<<Bc, 256>>>(beta);
        k_gemm2_update<<<dim3(Nc / 64, Bc / 64), 256>>>(W, state, tau, s);
        k_check<<<1, 1>>>(s);
    }
}

// round 3
// speedup vs baseline: 2.4374x; 2.4374x over previous
#include <cuda_runtime.h>
#include <cuda_bf16.h>
#include <cstdint>
#include <math.h>

// Problem dims (fixed by the dataset)
#define Bc 256
#define Nc 4096
#define Mc 16384
#define STEPS 50

// ---------------------------------------------------------------------------
// Device-global scratch (no allocations allowed)
// ---------------------------------------------------------------------------
__device__ __nv_bfloat16 g_Whi[(size_t)Mc * Nc];   // 128 MB  W hi  [m][n]
__device__ __nv_bfloat16 g_Wlo[(size_t)Mc * Nc];   // 128 MB  W lo
__device__ __nv_bfloat16 g_Wthi[(size_t)Nc * Mc];  // 128 MB  W^T hi [n][m]
__device__ __nv_bfloat16 g_Wtlo[(size_t)Nc * Mc];  // 128 MB  W^T lo
__device__ __nv_bfloat16 g_shi[(size_t)Bc * Nc];   // state hi [b][n]
__device__ __nv_bfloat16 g_slo[(size_t)Bc * Nc];   // state lo
__device__ __nv_bfloat16 g_fhi[(size_t)Bc * Mc];   // softmax hi [b][m]
__device__ __nv_bfloat16 g_flo[(size_t)Bc * Mc];   // softmax lo
__device__ float g_h[(size_t)Bc * Mc];             // 16 MB logits [b][m]
__device__ float g_vpart[4][(size_t)Bc * Nc];      // GEMM2 k-split partials
__device__ float g_norm[STEPS];
__device__ int   g_done;

// ---------------------------------------------------------------------------
// sm_80-era PTX helpers (legal on plain sm_103 target)
// ---------------------------------------------------------------------------
__device__ __forceinline__ uint32_t s2u(const void* p) {
    return (uint32_t)__cvta_generic_to_shared(p);
}
__device__ __forceinline__ void cpa16(uint32_t dst, const void* src) {
    asm volatile("cp.async.cg.shared.global [%0], [%1], 16;" :: "r"(dst), "l"(src));
}
#define CP_COMMIT() asm volatile("cp.async.commit_group;" ::: "memory")
#define CP_WAIT(n)  asm volatile("cp.async.wait_group %0;" :: "n"(n) : "memory")

__device__ __forceinline__ void ldm4(uint32_t* r, uint32_t addr) {
    asm volatile("ldmatrix.sync.aligned.m8n8.x4.shared.b16 {%0,%1,%2,%3}, [%4];"
                 : "=r"(r[0]), "=r"(r[1]), "=r"(r[2]), "=r"(r[3]) : "r"(addr));
}
__device__ __forceinline__ void mma16816(float* d, const uint32_t* a,
                                         uint32_t b0, uint32_t b1) {
    asm volatile(
        "mma.sync.aligned.m16n8k16.row.col.f32.bf16.bf16.f32 "
        "{%0,%1,%2,%3}, {%4,%5,%6,%7}, {%8,%9}, {%0,%1,%2,%3};"
        : "+f"(d[0]), "+f"(d[1]), "+f"(d[2]), "+f"(d[3])
        : "r"(a[0]), "r"(a[1]), "r"(a[2]), "r"(a[3]), "r"(b0), "r"(b1));
}

// ---------------------------------------------------------------------------
// Init: state <- input, split into bf16 hi/lo, reset flags
// ---------------------------------------------------------------------------
__global__ void k_init(const float* __restrict__ inp, float* __restrict__ state) {
    int i = blockIdx.x * blockDim.x + threadIdx.x;
    if (i < Bc * Nc) {
        float x = inp[i];
        state[i] = x;
        __nv_bfloat16 h = __float2bfloat16(x);
        g_shi[i] = h;
        g_slo[i] = __float2bfloat16(x - __bfloat162float(h));
    }
    if (i < STEPS) g_norm[i] = 0.0f;
    if (i == 0) g_done = 0;
}

// ---------------------------------------------------------------------------
// Split W into bf16 hi/lo + transposed copies (32x32 tiles through SMEM)
// ---------------------------------------------------------------------------
__global__ void __launch_bounds__(256) k_convW(const float* __restrict__ W) {
    __shared__ __nv_bfloat16 th[32][33];
    __shared__ __nv_bfloat16 tl[32][33];
    const int n0 = blockIdx.x * 32;
    const int m0 = blockIdx.y * 32;
    const int tx = threadIdx.x;   // 0..31
    const int ty = threadIdx.y;   // 0..7
#pragma unroll
    for (int i = 0; i < 4; i++) {
        int r = ty + i * 8;
        size_t gi = (size_t)(m0 + r) * Nc + n0 + tx;
        float x = W[gi];
        __nv_bfloat16 h = __float2bfloat16(x);
        __nv_bfloat16 l = __float2bfloat16(x - __bfloat162float(h));
        g_Whi[gi] = h;
        g_Wlo[gi] = l;
        th[r][tx] = h;
        tl[r][tx] = l;
    }
    __syncthreads();
#pragma unroll
    for (int i = 0; i < 4; i++) {
        int r = ty + i * 8;
        size_t gi = (size_t)(n0 + r) * Mc + m0 + tx;
        g_Wthi[gi] = th[tx][r];
        g_Wtlo[gi] = tl[tx][r];
    }
}

// ---------------------------------------------------------------------------
// Split-bf16 GEMM via mma.sync:
//   C[b][c] = sum_k A[b][k] * B[c][k]   (3 products: hh + hl + lh)
// CTA tile 128(b) x 128(c) x 32(k), 8 warps (4 row x 2 col), double-buffered
// cp.async. MODE 0: A=state,B=W -> g_h.  MODE 1: A=f,B=Wt -> g_vpart[z].
// ---------------------------------------------------------------------------
#define ROWB   80                  // smem row stride bytes (32 bf16 + 8 pad)
#define TILE_S (128 * ROWB)        // 10240 B per tile
#define STG_S  (4 * TILE_S)        // Ah, Al, Bh, Bl  = 40960 B
#define SMEM_T (2 * STG_S)         // 81920 B

__device__ __forceinline__ void load_stage(
    uint32_t sbase, int tid,
    const __nv_bfloat16* Ah, const __nv_bfloat16* Al,
    const __nv_bfloat16* Bh, const __nv_bfloat16* Bl,
    size_t ldA, size_t ldB)
{
#pragma unroll
    for (int t = 0; t < 2; t++) {
        int idx = tid + t * 256;       // 0..511
        int r = idx >> 2;              // 0..127
        int q = idx & 3;               // 16B segment
        uint32_t so = (uint32_t)(r * ROWB + q * 16);
        cpa16(sbase + 0 * TILE_S + so, Ah + (size_t)r * ldA + q * 8);
        cpa16(sbase + 1 * TILE_S + so, Al + (size_t)r * ldA + q * 8);
        cpa16(sbase + 2 * TILE_S + so, Bh + (size_t)r * ldB + q * 8);
        cpa16(sbase + 3 * TILE_S + so, Bl + (size_t)r * ldB + q * 8);
    }
}

template <int MODE>
__global__ void __launch_bounds__(256, 1) k_mma() {
    if (g_done) return;
    extern __shared__ char smem[];
    const int tid = threadIdx.x;
    const int wid = tid >> 5;
    const int lid = tid & 31;
    const int rw  = wid & 3;          // warp row (b): 32 rows each
    const int cw  = wid >> 2;         // warp col:     64 cols each
    const uint32_t sb = s2u(smem);

    constexpr size_t ldA = MODE ? (size_t)Mc : (size_t)Nc;
    constexpr size_t ldB = ldA;
    constexpr size_t ldO = MODE ? (size_t)Nc : (size_t)Mc;
    constexpr int NCHUNK = 128;       // K = 4096 per kernel / 32

    const int b0 = blockIdx.x * 128;
    const int c0 = blockIdx.y * 128;
    const size_t koff = (size_t)blockIdx.z * 4096;

    const __nv_bfloat16* Ahp = (MODE ? g_fhi : g_shi) + (size_t)b0 * ldA + koff;
    const __nv_bfloat16* Alp = (MODE ? g_flo : g_slo) + (size_t)b0 * ldA + koff;
    const __nv_bfloat16* Bhp = (MODE ? g_Wthi : g_Whi) + (size_t)c0 * ldB + koff;
    const __nv_bfloat16* Blp = (MODE ? g_Wtlo : g_Wlo) + (size_t)c0 * ldB + koff;
    float* out = MODE ? &g_vpart[blockIdx.z][0] : g_h;

    float acc[2][8][4];
#pragma unroll
    for (int i = 0; i < 2; i++)
#pragma unroll
        for (int j = 0; j < 8; j++)
#pragma unroll
            for (int v = 0; v < 4; v++) acc[i][j][v] = 0.0f;

    // ldmatrix lane addressing pieces
    const int lrow = ((lid >> 3) & 1) * 8 + (lid & 7);  // row within 16-row block
    const int lkb  = (lid >> 4) * 16;                   // 0 or 16 bytes (k half)

    load_stage(sb, tid, Ahp, Alp, Bhp, Blp, ldA, ldB);
    CP_COMMIT();

    for (int ch = 0; ch < NCHUNK; ++ch) {
        const uint32_t cur = sb + (uint32_t)(ch & 1) * STG_S;
        if (ch + 1 < NCHUNK) {
            const size_t kk = (size_t)(ch + 1) * 32;
            load_stage(sb + (uint32_t)((ch + 1) & 1) * STG_S, tid,
                       Ahp + kk, Alp + kk, Bhp + kk, Blp + kk, ldA, ldB);
            CP_COMMIT();
            CP_WAIT(1);
        } else {
            CP_WAIT(0);
        }
        __syncthreads();

#pragma unroll
        for (int ks = 0; ks < 2; ++ks) {           // two k16 steps
            const uint32_t kbyte = (uint32_t)(ks * 32 + lkb);
            uint32_t aF[2][2][4];                  // [hi/lo][sub][reg]
            uint32_t bF[2][4][4];                  // [hi/lo][colgrp][reg]
#pragma unroll
            for (int sub = 0; sub < 2; ++sub) {
                uint32_t ra = (uint32_t)((rw * 32 + sub * 16 + lrow) * ROWB) + kbyte;
                ldm4(aF[0][sub], cur + 0 * TILE_S + ra);
                ldm4(aF[1][sub], cur + 1 * TILE_S + ra);
            }
#pragma unroll
            for (int cg = 0; cg < 4; ++cg) {
                uint32_t rb = (uint32_t)((cw * 64 + cg * 16 + lrow) * ROWB) + kbyte;
                ldm4(bF[0][cg], cur + 2 * TILE_S + rb);
                ldm4(bF[1][cg], cur + 3 * TILE_S + rb);
            }
#pragma unroll
            for (int sub = 0; sub < 2; ++sub) {
#pragma unroll
                for (int cg = 0; cg < 4; ++cg) {
#pragma unroll
                    for (int hf = 0; hf < 2; ++hf) {
                        const int nt = cg * 2 + hf;
                        // hh
                        mma16816(acc[sub][nt], aF[0][sub],
                                 bF[0][cg][hf], bF[0][cg][hf + 2]);
                        // h*lo
                        mma16816(acc[sub][nt], aF[0][sub],
                                 bF[1][cg][hf], bF[1][cg][hf + 2]);
                        // lo*h
                        mma16816(acc[sub][nt], aF[1][sub],
                                 bF[0][cg][hf], bF[0][cg][hf + 2]);
                    }
                }
            }
        }
        __syncthreads();
    }

    // Epilogue: write fp32 output
    const int gr = lid >> 2;          // 0..7
    const int gc = (lid & 3) * 2;     // 0,2,4,6
#pragma unroll
    for (int sub = 0; sub < 2; ++sub) {
        const int rbase = b0 + rw * 32 + sub * 16 + gr;
#pragma unroll
        for (int nt = 0; nt < 8; ++nt) {
            const int col = c0 + cw * 64 + nt * 8 + gc;
            float* p0 = out + (size_t)rbase * ldO + col;
            float* p1 = out + (size_t)(rbase + 8) * ldO + col;
            *(float2*)p0 = make_float2(acc[sub][nt][0], acc[sub][nt][1]);
            *(float2*)p1 = make_float2(acc[sub][nt][2], acc[sub][nt][3]);
        }
    }
}

// ---------------------------------------------------------------------------
// Softmax over memory dim per batch row; writes split-bf16 probs
// ---------------------------------------------------------------------------
__global__ void __launch_bounds__(256) k_softmax(const float* __restrict__ beta_p) {
    if (g_done) return;
    const int b   = blockIdx.x;
    const int tid = threadIdx.x;
    const float beta = *beta_p;
    float* row = g_h + (size_t)b * Mc;
    __shared__ float red[256];

    float mx = -3.402823466e38f;
    for (int m = tid; m < Mc; m += 256) mx = fmaxf(mx, beta * row[m]);
    red[tid] = mx;
    __syncthreads();
    for (int s = 128; s > 0; s >>= 1) {
        if (tid < s) red[tid] = fmaxf(red[tid], red[tid + s]);
        __syncthreads();
    }
    mx = red[0];
    __syncthreads();

    float sum = 0.0f;
    for (int m = tid; m < Mc; m += 256) {
        float e = expf(beta * row[m] - mx);
        row[m] = e;
        sum += e;
    }
    red[tid] = sum;
    __syncthreads();
    for (int s = 128; s > 0; s >>= 1) {
        if (tid < s) red[tid] += red[tid + s];
        __syncthreads();
    }
    const float inv = 1.0f / red[0];

    for (int m = tid; m < Mc; m += 256) {
        float p = row[m] * inv;
        __nv_bfloat16 h = __float2bfloat16(p);
        g_fhi[(size_t)b * Mc + m] = h;
        g_flo[(size_t)b * Mc + m] = __float2bfloat16(p - __bfloat162float(h));
    }
}

// ---------------------------------------------------------------------------
// Combine k-split partials + state update + norm + re-split state to bf16
// ---------------------------------------------------------------------------
__global__ void __launch_bounds__(256) k_update(float* __restrict__ state,
                                                const float* __restrict__ tau_p,
                                                int step) {
    if (g_done) return;
    __shared__ float red[256];
    const int tid = threadIdx.x;
    const int i = blockIdx.x * 256 + tid;

    float v = g_vpart[0][i] + g_vpart[1][i] + g_vpart[2][i] + g_vpart[3][i];
    float so = state[i];
    float nv = so + (1.0f / (*tau_p)) * (v - so);
    float d = nv - so;
    state[i] = nv;
    __nv_bfloat16 h = __float2bfloat16(nv);
    g_shi[i] = h;
    g_slo[i] = __float2bfloat16(nv - __bfloat162float(h));

    red[tid] = d * d;
    __syncthreads();
    for (int s = 128; s > 0; s >>= 1) {
        if (tid < s) red[tid] += red[tid + s];
        __syncthreads();
    }
    if (tid == 0) atomicAdd(&g_norm[step], red[0]);
}

__global__ void k_check(int step) {
    if (!g_done && sqrtf(g_norm[step]) <= 1e-3f) g_done = 1;
}

// ---------------------------------------------------------------------------
// kernel_launch
// ---------------------------------------------------------------------------
extern "C" void kernel_launch(void* const* d_in, const int* in_sizes, int n_in,
                              void* d_out, int out_size) {
    const float* inp  = (const float*)d_in[0];
    const float* W    = (const float*)d_in[1];
    const float* beta = (const float*)d_in[2];
    const float* tau  = (const float*)d_in[3];
    float* state = (float*)d_out;

    cudaFuncSetAttribute(k_mma<0>, cudaFuncAttributeMaxDynamicSharedMemorySize, SMEM_T);
    cudaFuncSetAttribute(k_mma<1>, cudaFuncAttributeMaxDynamicSharedMemorySize, SMEM_T);

    k_init<<<(Bc * Nc + 255) / 256, 256>>>(inp, state);
    k_convW<<<dim3(Nc / 32, Mc / 32), dim3(32, 8)>>>(W);

    for (int s = 0; s < STEPS; s++) {
        // GEMM1: x = b-tiles (2), y = m-tiles (128) -> b-pairs share W via L2
        k_mma<0><<<dim3(Bc / 128, Mc / 128, 1), 256, SMEM_T>>>();
        k_softmax<<<Bc, 256>>>(beta);
        // GEMM2: k-split x4 over M for occupancy
        k_mma<1><<<dim3(Bc / 128, Nc / 128, 4), 256, SMEM_T>>>();
        k_update<<<(Bc * Nc) / 256, 256>>>(state, tau, s);
        k_check<<<1, 1>>>(s);
    }
}

// round 4
// speedup vs baseline: 2.7840x; 1.1422x over previous
#include <cuda_runtime.h>
#include <cuda_bf16.h>
#include <cstdint>
#include <math.h>

// Problem dims (fixed by the dataset)
#define Bc 256
#define Nc 4096
#define Mc 16384
#define STEPS 50

// ---------------------------------------------------------------------------
// Device-global scratch (no allocations allowed)
// ---------------------------------------------------------------------------
__device__ __nv_bfloat16 g_Whi[(size_t)Mc * Nc];   // W hi  [m][n]
__device__ __nv_bfloat16 g_Wlo[(size_t)Mc * Nc];   // W lo
__device__ __nv_bfloat16 g_Wthi[(size_t)Nc * Mc];  // W^T hi [n][m]
__device__ __nv_bfloat16 g_Wtlo[(size_t)Nc * Mc];  // W^T lo
__device__ __nv_bfloat16 g_shi[(size_t)Bc * Nc];   // state hi [b][n]
__device__ __nv_bfloat16 g_slo[(size_t)Bc * Nc];   // state lo
__device__ __nv_bfloat16 g_fhi[(size_t)Bc * Mc];   // softmax hi [b][m]
__device__ __nv_bfloat16 g_flo[(size_t)Bc * Mc];   // softmax lo
__device__ float g_h[(size_t)Bc * Mc];             // logits [b][m]
__device__ float g_vpart[4][(size_t)Bc * Nc];      // GEMM2 k-split partials
__device__ float g_norm[STEPS];

// global barrier state (self-resetting; g_gen monotonic across replays)
__device__ unsigned g_cnt_bar;            // zero-initialized, returns to 0
__device__ volatile unsigned g_gen_bar;

// ---------------------------------------------------------------------------
// sm_80-era PTX helpers (legal on plain sm_103 target)
// ---------------------------------------------------------------------------
__device__ __forceinline__ uint32_t s2u(const void* p) {
    return (uint32_t)__cvta_generic_to_shared(p);
}
__device__ __forceinline__ void cpa16(uint32_t dst, const void* src) {
    asm volatile("cp.async.cg.shared.global [%0], [%1], 16;" :: "r"(dst), "l"(src));
}
#define CP_COMMIT() asm volatile("cp.async.commit_group;" ::: "memory")
#define CP_WAIT(n)  asm volatile("cp.async.wait_group %0;" :: "n"(n) : "memory")

__device__ __forceinline__ void ldm4(uint32_t* r, uint32_t addr) {
    asm volatile("ldmatrix.sync.aligned.m8n8.x4.shared.b16 {%0,%1,%2,%3}, [%4];"
                 : "=r"(r[0]), "=r"(r[1]), "=r"(r[2]), "=r"(r[3]) : "r"(addr));
}
__device__ __forceinline__ void mma16816(float* d, const uint32_t* a,
                                         uint32_t b0, uint32_t b1) {
    asm volatile(
        "mma.sync.aligned.m16n8k16.row.col.f32.bf16.bf16.f32 "
        "{%0,%1,%2,%3}, {%4,%5,%6,%7}, {%8,%9}, {%0,%1,%2,%3};"
        : "+f"(d[0]), "+f"(d[1]), "+f"(d[2]), "+f"(d[3])
        : "r"(a[0]), "r"(a[1]), "r"(a[2]), "r"(a[3]), "r"(b0), "r"(b1));
}

// ---------------------------------------------------------------------------
// Software global barrier. Safe because grid == #SMs and smem usage forces
// exactly 1 CTA/SM -> all CTAs are co-resident.
// ---------------------------------------------------------------------------
__device__ __forceinline__ void gbar(int G) {
    __syncthreads();
    if (threadIdx.x == 0) {
        __threadfence();
        unsigned my = g_gen_bar;
        unsigned old = atomicAdd(&g_cnt_bar, 1u);
        if (old == (unsigned)G - 1u) {
            g_cnt_bar = 0u;
            __threadfence();
            g_gen_bar = my + 1u;
        } else {
            while (g_gen_bar == my) __nanosleep(64);
        }
        __threadfence();
    }
    __syncthreads();
}

// ---------------------------------------------------------------------------
// Init: state <- input, split into bf16 hi/lo, reset norms
// ---------------------------------------------------------------------------
__global__ void k_init(const float* __restrict__ inp, float* __restrict__ state) {
    int i = blockIdx.x * blockDim.x + threadIdx.x;
    if (i < Bc * Nc) {
        float x = inp[i];
        state[i] = x;
        __nv_bfloat16 h = __float2bfloat16(x);
        g_shi[i] = h;
        g_slo[i] = __float2bfloat16(x - __bfloat162float(h));
    }
    if (i < STEPS) g_norm[i] = 0.0f;
}

// ---------------------------------------------------------------------------
// Split W into bf16 hi/lo + transposed copies (32x32 tiles through SMEM)
// ---------------------------------------------------------------------------
__global__ void __launch_bounds__(256) k_convW(const float* __restrict__ W) {
    __shared__ __nv_bfloat16 th[32][33];
    __shared__ __nv_bfloat16 tl[32][33];
    const int n0 = blockIdx.x * 32;
    const int m0 = blockIdx.y * 32;
    const int tx = threadIdx.x;
    const int ty = threadIdx.y;
#pragma unroll
    for (int i = 0; i < 4; i++) {
        int r = ty + i * 8;
        size_t gi = (size_t)(m0 + r) * Nc + n0 + tx;
        float x = W[gi];
        __nv_bfloat16 h = __float2bfloat16(x);
        __nv_bfloat16 l = __float2bfloat16(x - __bfloat162float(h));
        g_Whi[gi] = h;
        g_Wlo[gi] = l;
        th[r][tx] = h;
        tl[r][tx] = l;
    }
    __syncthreads();
#pragma unroll
    for (int i = 0; i < 4; i++) {
        int r = ty + i * 8;
        size_t gi = (size_t)(n0 + r) * Mc + m0 + tx;
        g_Wthi[gi] = th[tx][r];
        g_Wtlo[gi] = tl[tx][r];
    }
}

// ---------------------------------------------------------------------------
// GEMM tile: C[128(b) x 128(c)] += A[b][k] * B[c][k] over K=4096, split-bf16
// (hh + hl + lh). 16 warps in 4(b) x 4(c); per warp 32x32. 3-stage cp.async.
// ---------------------------------------------------------------------------
#define ROWB   80                  // smem row stride (32 bf16 + 8B pad) - LDSM conflict-free
#define TILE_S (128 * ROWB)        // 10240 B
#define STG_S  (4 * TILE_S)        // Ah, Al, Bh, Bl = 40960 B per stage
#define NSTG   3
#define SMEM_T (NSTG * STG_S)      // 122880 B
#define NCH    128                 // 4096 / 32

__device__ __forceinline__ void load_stage(
    uint32_t sbase, int tid,
    const __nv_bfloat16* Ah, const __nv_bfloat16* Al,
    const __nv_bfloat16* Bh, const __nv_bfloat16* Bl, size_t ld)
{
    int r = tid >> 2;              // 0..127
    int q = tid & 3;
    uint32_t so = (uint32_t)(r * ROWB + q * 16);
    const size_t go = (size_t)r * ld + q * 8;
    cpa16(sbase + 0 * TILE_S + so, Ah + go);
    cpa16(sbase + 1 * TILE_S + so, Al + go);
    cpa16(sbase + 2 * TILE_S + so, Bh + go);
    cpa16(sbase + 3 * TILE_S + so, Bl + go);
}

template <int MODE>
__device__ void gemm_tile(char* smem, int t) {
    const int tid = threadIdx.x;
    const int wid = tid >> 5;
    const int lid = tid & 31;
    const int rw  = wid & 3;       // warp b-row: 32 rows
    const int cw  = wid >> 2;      // warp c-col: 32 cols
    const uint32_t sb = s2u(smem);

    constexpr size_t ld  = MODE ? (size_t)Mc : (size_t)Nc;
    constexpr size_t ldO = MODE ? (size_t)Nc : (size_t)Mc;

    const int b0 = (t & 1) * 128;
    int c0, z;
    if (MODE) { z = t >> 6; c0 = ((t >> 1) & 31) * 128; }
    else      { z = 0;      c0 = (t >> 1) * 128; }
    const size_t koff = (size_t)z * 4096;

    const __nv_bfloat16* Ahp = (MODE ? g_fhi : g_shi) + (size_t)b0 * ld + koff;
    const __nv_bfloat16* Alp = (MODE ? g_flo : g_slo) + (size_t)b0 * ld + koff;
    const __nv_bfloat16* Bhp = (MODE ? g_Wthi : g_Whi) + (size_t)c0 * ld + koff;
    const __nv_bfloat16* Blp = (MODE ? g_Wtlo : g_Wlo) + (size_t)c0 * ld + koff;
    float* out = MODE ? &g_vpart[z][0] : g_h;

    float acc[2][4][4];
#pragma unroll
    for (int i = 0; i < 2; i++)
#pragma unroll
        for (int j = 0; j < 4; j++)
#pragma unroll
            for (int v = 0; v < 4; v++) acc[i][j][v] = 0.0f;

    const int lrow = ((lid >> 3) & 1) * 8 + (lid & 7);
    const int lkb  = (lid >> 4) * 16;

    load_stage(sb + 0 * STG_S, tid, Ahp, Alp, Bhp, Blp, ld);
    CP_COMMIT();
    load_stage(sb + 1 * STG_S, tid, Ahp + 32, Alp + 32, Bhp + 32, Blp + 32, ld);
    CP_COMMIT();

    for (int ch = 0; ch < NCH; ++ch) {
        const uint32_t cur = sb + (uint32_t)(ch % NSTG) * STG_S;
        if (ch + 2 < NCH) {
            CP_WAIT(1);
            __syncthreads();
            const size_t kk = (size_t)(ch + 2) * 32;
            load_stage(sb + (uint32_t)((ch + 2) % NSTG) * STG_S, tid,
                       Ahp + kk, Alp + kk, Bhp + kk, Blp + kk, ld);
            CP_COMMIT();
        } else {
            CP_WAIT(0);
            __syncthreads();
        }

#pragma unroll
        for (int ks = 0; ks < 2; ++ks) {
            const uint32_t kbyte = (uint32_t)(ks * 32 + lkb);
            uint32_t aF[2][2][4];              // [hi/lo][sub]
            uint32_t bF[2][2][4];              // [hi/lo][cg]
#pragma unroll
            for (int sub = 0; sub < 2; ++sub) {
                uint32_t ra = (uint32_t)((rw * 32 + sub * 16 + lrow) * ROWB) + kbyte;
                ldm4(aF[0][sub], cur + 0 * TILE_S + ra);
                ldm4(aF[1][sub], cur + 1 * TILE_S + ra);
            }
#pragma unroll
            for (int cg = 0; cg < 2; ++cg) {
                uint32_t rb = (uint32_t)((cw * 32 + cg * 16 + lrow) * ROWB) + kbyte;
                ldm4(bF[0][cg], cur + 2 * TILE_S + rb);
                ldm4(bF[1][cg], cur + 3 * TILE_S + rb);
            }
#pragma unroll
            for (int sub = 0; sub < 2; ++sub) {
#pragma unroll
                for (int cg = 0; cg < 2; ++cg) {
#pragma unroll
                    for (int hf = 0; hf < 2; ++hf) {
                        const int nt = cg * 2 + hf;
                        mma16816(acc[sub][nt], aF[0][sub],
                                 bF[0][cg][hf], bF[0][cg][hf + 2]);   // hh
                        mma16816(acc[sub][nt], aF[0][sub],
                                 bF[1][cg][hf], bF[1][cg][hf + 2]);   // h*lo
                        mma16816(acc[sub][nt], aF[1][sub],
                                 bF[0][cg][hf], bF[0][cg][hf + 2]);   // lo*h
                    }
                }
            }
        }
        __syncthreads();
    }

    const int gr = lid >> 2;
    const int gc = (lid & 3) * 2;
#pragma unroll
    for (int sub = 0; sub < 2; ++sub) {
        const int rbase = b0 + rw * 32 + sub * 16 + gr;
#pragma unroll
        for (int nt = 0; nt < 4; ++nt) {
            const int col = c0 + cw * 32 + nt * 8 + gc;
            float* p0 = out + (size_t)rbase * ldO + col;
            float* p1 = out + (size_t)(rbase + 8) * ldO + col;
            *(float2*)p0 = make_float2(acc[sub][nt][0], acc[sub][nt][1]);
            *(float2*)p1 = make_float2(acc[sub][nt][2], acc[sub][nt][3]);
        }
    }
}

// ---------------------------------------------------------------------------
// Softmax over memory dim for one batch row (512 threads); split-bf16 out
// ---------------------------------------------------------------------------
__device__ void softmax_row(int b, float beta, float* red) {
    const int tid = threadIdx.x;
    float* row = g_h + (size_t)b * Mc;

    float mx = -3.402823466e38f;
    for (int m = tid; m < Mc; m += 512) mx = fmaxf(mx, beta * row[m]);
    red[tid] = mx;
    __syncthreads();
    for (int s = 256; s > 0; s >>= 1) {
        if (tid < s) red[tid] = fmaxf(red[tid], red[tid + s]);
        __syncthreads();
    }
    mx = red[0];
    __syncthreads();

    float sum = 0.0f;
    for (int m = tid; m < Mc; m += 512) {
        float e = expf(beta * row[m] - mx);
        row[m] = e;
        sum += e;
    }
    red[tid] = sum;
    __syncthreads();
    for (int s = 256; s > 0; s >>= 1) {
        if (tid < s) red[tid] += red[tid + s];
        __syncthreads();
    }
    const float inv = 1.0f / red[0];
    __syncthreads();

    for (int m = tid; m < Mc; m += 512) {
        float p = row[m] * inv;
        __nv_bfloat16 h = __float2bfloat16(p);
        g_fhi[(size_t)b * Mc + m] = h;
        g_flo[(size_t)b * Mc + m] = __float2bfloat16(p - __bfloat162float(h));
    }
}

// ---------------------------------------------------------------------------
// Persistent kernel: all 50 fixed-point steps with device-side convergence
// ---------------------------------------------------------------------------
__global__ void __launch_bounds__(512, 1) k_steps(float* __restrict__ state,
                                                  const float* __restrict__ beta_p,
                                                  const float* __restrict__ tau_p,
                                                  int G) {
    extern __shared__ char smem[];
    float* red = (float*)smem;
    const int tid = threadIdx.x;
    const float beta = *beta_p;
    const float invtau = 1.0f / (*tau_p);

    for (int step = 0; step < STEPS; ++step) {
        // GEMM1: h = s . W^T  (256 tiles: b-pair x 128 m-tiles)
        for (int t = blockIdx.x; t < 256; t += G) gemm_tile<0>(smem, t);
        gbar(G);

        // Softmax rows
        for (int b = blockIdx.x; b < Bc; b += G) softmax_row(b, beta, red);
        gbar(G);

        // GEMM2: v = f . W (k-split x4 -> g_vpart)
        for (int t = blockIdx.x; t < 256; t += G) gemm_tile<1>(smem, t);
        gbar(G);

        // Update + norm
        float sumsq = 0.0f;
        for (int i = blockIdx.x * 512 + tid; i < Bc * Nc; i += G * 512) {
            float v = g_vpart[0][i] + g_vpart[1][i] + g_vpart[2][i] + g_vpart[3][i];
            float so = state[i];
            float nv = so + invtau * (v - so);
            float d = nv - so;
            sumsq += d * d;
            state[i] = nv;
            __nv_bfloat16 h = __float2bfloat16(nv);
            g_shi[i] = h;
            g_slo[i] = __float2bfloat16(nv - __bfloat162float(h));
        }
        red[tid] = sumsq;
        __syncthreads();
        for (int s = 256; s > 0; s >>= 1) {
            if (tid < s) red[tid] += red[tid + s];
            __syncthreads();
        }
        if (tid == 0) atomicAdd(&g_norm[step], red[0]);
        gbar(G);

        // Uniform convergence decision (freeze = stop doing work)
        float nrm = *(volatile float*)&g_norm[step];
        if (sqrtf(nrm) <= 1e-3f) break;
        __syncthreads();
    }
}

// ---------------------------------------------------------------------------
// kernel_launch
// ---------------------------------------------------------------------------
extern "C" void kernel_launch(void* const* d_in, const int* in_sizes, int n_in,
                              void* d_out, int out_size) {
    const float* inp  = (const float*)d_in[0];
    const float* W    = (const float*)d_in[1];
    const float* beta = (const float*)d_in[2];
    const float* tau  = (const float*)d_in[3];
    float* state = (float*)d_out;

    int dev = 0;
    cudaGetDevice(&dev);
    cudaDeviceProp props;
    cudaGetDeviceProperties(&props, dev);
    const int G = props.multiProcessorCount;

    cudaFuncSetAttribute(k_steps, cudaFuncAttributeMaxDynamicSharedMemorySize, SMEM_T);

    k_init<<<(Bc * Nc + 255) / 256, 256>>>(inp, state);
    k_convW<<<dim3(Nc / 32, Mc / 32), dim3(32, 8)>>>(W);
    k_steps<<<G, 512, SMEM_T>>>(state, beta, tau, G);
}

// round 5
// speedup vs baseline: 3.7430x; 1.3445x over previous
#include <cuda_runtime.h>
#include <cuda_bf16.h>
#include <cuda_fp16.h>
#include <cstdint>
#include <math.h>

// Problem dims (fixed by the dataset)
#define Bc 256
#define Nc 4096
#define Mc 16384
#define STEPS 50
#define FSCALE 4096.0f          // softmax-prob scaling (keeps fp16 lo normal)
#define INV_FSCALE (1.0f / 4096.0f)

// ---------------------------------------------------------------------------
// Device-global scratch (no allocations allowed)
// ---------------------------------------------------------------------------
__device__ __half g_Wh [(size_t)Mc * Nc];   // 128 MB  W fp16   [m][n]
__device__ __half g_Wth[(size_t)Nc * Mc];   // 128 MB  W^T fp16 [n][m]
__device__ __half g_shi[(size_t)Bc * Nc];   // state hi [b][n]
__device__ __half g_slo[(size_t)Bc * Nc];   // state lo
__device__ __half g_fhi[(size_t)Bc * Mc];   // probs*FSCALE hi [b][m]
__device__ __half g_flo[(size_t)Bc * Mc];   // probs*FSCALE lo
__device__ float  g_h[(size_t)Bc * Mc];     // logits [b][m]
__device__ float  g_vpart[4][(size_t)Bc * Nc];
__device__ float  g_norm[STEPS];

// global barrier state (self-resetting; g_gen monotonic across replays)
__device__ unsigned g_cnt_bar;
__device__ volatile unsigned g_gen_bar;

// ---------------------------------------------------------------------------
// sm_80-era PTX helpers (legal on plain sm_103 target)
// ---------------------------------------------------------------------------
__device__ __forceinline__ uint32_t s2u(const void* p) {
    return (uint32_t)__cvta_generic_to_shared(p);
}
__device__ __forceinline__ void cpa16(uint32_t dst, const void* src) {
    asm volatile("cp.async.cg.shared.global [%0], [%1], 16;" :: "r"(dst), "l"(src));
}
#define CP_COMMIT() asm volatile("cp.async.commit_group;" ::: "memory")
#define CP_WAIT(n)  asm volatile("cp.async.wait_group %0;" :: "n"(n) : "memory")

__device__ __forceinline__ void ldm4(uint32_t* r, uint32_t addr) {
    asm volatile("ldmatrix.sync.aligned.m8n8.x4.shared.b16 {%0,%1,%2,%3}, [%4];"
                 : "=r"(r[0]), "=r"(r[1]), "=r"(r[2]), "=r"(r[3]) : "r"(addr));
}
__device__ __forceinline__ void mma16816(float* d, const uint32_t* a,
                                         uint32_t b0, uint32_t b1) {
    asm volatile(
        "mma.sync.aligned.m16n8k16.row.col.f32.f16.f16.f32 "
        "{%0,%1,%2,%3}, {%4,%5,%6,%7}, {%8,%9}, {%0,%1,%2,%3};"
        : "+f"(d[0]), "+f"(d[1]), "+f"(d[2]), "+f"(d[3])
        : "r"(a[0]), "r"(a[1]), "r"(a[2]), "r"(a[3]), "r"(b0), "r"(b1));
}

// ---------------------------------------------------------------------------
// Software global barrier (grid == #SMs, 1 CTA/SM -> all co-resident)
// ---------------------------------------------------------------------------
__device__ __forceinline__ void gbar(int G) {
    __syncthreads();
    if (threadIdx.x == 0) {
        __threadfence();
        unsigned my = g_gen_bar;
        unsigned old = atomicAdd(&g_cnt_bar, 1u);
        if (old == (unsigned)G - 1u) {
            g_cnt_bar = 0u;
            __threadfence();
            g_gen_bar = my + 1u;
        } else {
            while (g_gen_bar == my) __nanosleep(64);
        }
        __threadfence();
    }
    __syncthreads();
}

// ---------------------------------------------------------------------------
// Init: state <- input, split into fp16 hi/lo, reset norms
// ---------------------------------------------------------------------------
__global__ void k_init(const float* __restrict__ inp, float* __restrict__ state) {
    int i = blockIdx.x * blockDim.x + threadIdx.x;
    if (i < Bc * Nc) {
        float x = inp[i];
        state[i] = x;
        __half h = __float2half(x);
        g_shi[i] = h;
        g_slo[i] = __float2half(x - __half2float(h));
    }
    if (i < STEPS) g_norm[i] = 0.0f;
}

// ---------------------------------------------------------------------------
// W -> fp16 + fp16 transpose (32x32 tiles through SMEM)
// ---------------------------------------------------------------------------
__global__ void __launch_bounds__(256) k_convW(const float* __restrict__ W) {
    __shared__ __half th[32][33];
    const int n0 = blockIdx.x * 32;
    const int m0 = blockIdx.y * 32;
    const int tx = threadIdx.x;
    const int ty = threadIdx.y;
#pragma unroll
    for (int i = 0; i < 4; i++) {
        int r = ty + i * 8;
        size_t gi = (size_t)(m0 + r) * Nc + n0 + tx;
        __half h = __float2half(W[gi]);
        g_Wh[gi] = h;
        th[r][tx] = h;
    }
    __syncthreads();
#pragma unroll
    for (int i = 0; i < 4; i++) {
        int r = ty + i * 8;
        g_Wth[(size_t)(n0 + r) * Mc + m0 + tx] = th[tx][r];
    }
}

// ---------------------------------------------------------------------------
// GEMM tile: C[128(b) x 128(c)] += (Ah+Al)[b][k] * B[c][k] over K=4096.
// 2 MMA products (fp16 split activations, single-fp16 W).
// 16 warps in 4(b) x 4(c); 32x32 per warp; 3-stage cp.async.
// ---------------------------------------------------------------------------
#define ROWB   80                  // smem row stride (32 fp16 + 8B pad)
#define TILE_S (128 * ROWB)        // 10240 B
#define STG_S  (3 * TILE_S)        // Ah, Al, B = 30720 B per stage
#define NSTG   3
#define SMEM_T (NSTG * STG_S)      // 92160 B
#define NCH    128                 // 4096 / 32

__device__ __forceinline__ void load_stage(
    uint32_t sbase, int tid,
    const __half* Ah, const __half* Al, const __half* B, size_t ld)
{
    int r = tid >> 2;              // 0..127
    int q = tid & 3;
    uint32_t so = (uint32_t)(r * ROWB + q * 16);
    const size_t go = (size_t)r * ld + q * 8;
    cpa16(sbase + 0 * TILE_S + so, Ah + go);
    cpa16(sbase + 1 * TILE_S + so, Al + go);
    cpa16(sbase + 2 * TILE_S + so, B + go);
}

template <int MODE>
__device__ void gemm_tile(char* smem, int t) {
    const int tid = threadIdx.x;
    const int wid = tid >> 5;
    const int lid = tid & 31;
    const int rw  = wid & 3;       // warp b-row (32 rows)
    const int cw  = wid >> 2;      // warp c-col (32 cols)
    const uint32_t sb = s2u(smem);

    constexpr size_t ld  = MODE ? (size_t)Mc : (size_t)Nc;
    constexpr size_t ldO = MODE ? (size_t)Nc : (size_t)Mc;

    const int b0 = (t & 1) * 128;
    int c0, z;
    if (MODE) { z = t >> 6; c0 = ((t >> 1) & 31) * 128; }
    else      { z = 0;      c0 = (t >> 1) * 128; }
    const size_t koff = (size_t)z * 4096;

    const __half* Ahp = (MODE ? g_fhi : g_shi) + (size_t)b0 * ld + koff;
    const __half* Alp = (MODE ? g_flo : g_slo) + (size_t)b0 * ld + koff;
    const __half* Bp  = (MODE ? g_Wth : g_Wh) + (size_t)c0 * ld + koff;
    float* out = MODE ? &g_vpart[z][0] : g_h;

    float acc[2][4][4];
#pragma unroll
    for (int i = 0; i < 2; i++)
#pragma unroll
        for (int j = 0; j < 4; j++)
#pragma unroll
            for (int v = 0; v < 4; v++) acc[i][j][v] = 0.0f;

    const int lrow = ((lid >> 3) & 1) * 8 + (lid & 7);
    const int lkb  = (lid >> 4) * 16;

    load_stage(sb + 0 * STG_S, tid, Ahp, Alp, Bp, ld);
    CP_COMMIT();
    load_stage(sb + 1 * STG_S, tid, Ahp + 32, Alp + 32, Bp + 32, ld);
    CP_COMMIT();

    for (int ch = 0; ch < NCH; ++ch) {
        const uint32_t cur = sb + (uint32_t)(ch % NSTG) * STG_S;
        if (ch + 2 < NCH) {
            CP_WAIT(1);
            __syncthreads();
            const size_t kk = (size_t)(ch + 2) * 32;
            load_stage(sb + (uint32_t)((ch + 2) % NSTG) * STG_S, tid,
                       Ahp + kk, Alp + kk, Bp + kk, ld);
            CP_COMMIT();
        } else {
            CP_WAIT(0);
            __syncthreads();
        }

#pragma unroll
        for (int ks = 0; ks < 2; ++ks) {
            const uint32_t kbyte = (uint32_t)(ks * 32 + lkb);
            uint32_t aF[2][2][4];              // [hi/lo][sub]
            uint32_t bF[2][4];                 // [cg]
#pragma unroll
            for (int sub = 0; sub < 2; ++sub) {
                uint32_t ra = (uint32_t)((rw * 32 + sub * 16 + lrow) * ROWB) + kbyte;
                ldm4(aF[0][sub], cur + 0 * TILE_S + ra);
                ldm4(aF[1][sub], cur + 1 * TILE_S + ra);
            }
#pragma unroll
            for (int cg = 0; cg < 2; ++cg) {
                uint32_t rb = (uint32_t)((cw * 32 + cg * 16 + lrow) * ROWB) + kbyte;
                ldm4(bF[cg], cur + 2 * TILE_S + rb);
            }
#pragma unroll
            for (int sub = 0; sub < 2; ++sub) {
#pragma unroll
                for (int cg = 0; cg < 2; ++cg) {
#pragma unroll
                    for (int hf = 0; hf < 2; ++hf) {
                        const int nt = cg * 2 + hf;
                        mma16816(acc[sub][nt], aF[0][sub],
                                 bF[cg][hf], bF[cg][hf + 2]);   // Ah * W
                        mma16816(acc[sub][nt], aF[1][sub],
                                 bF[cg][hf], bF[cg][hf + 2]);   // Al * W
                    }
                }
            }
        }
        __syncthreads();
    }

    const int gr = lid >> 2;
    const int gc = (lid & 3) * 2;
#pragma unroll
    for (int sub = 0; sub < 2; ++sub) {
        const int rbase = b0 + rw * 32 + sub * 16 + gr;
#pragma unroll
        for (int nt = 0; nt < 4; ++nt) {
            const int col = c0 + cw * 32 + nt * 8 + gc;
            float* p0 = out + (size_t)rbase * ldO + col;
            float* p1 = out + (size_t)(rbase + 8) * ldO + col;
            *(float2*)p0 = make_float2(acc[sub][nt][0], acc[sub][nt][1]);
            *(float2*)p1 = make_float2(acc[sub][nt][2], acc[sub][nt][3]);
        }
    }
}

// ---------------------------------------------------------------------------
// Softmax over memory dim for one batch row (512 threads); scaled fp16 split
// ---------------------------------------------------------------------------
__device__ void softmax_row(int b, float beta, float* red) {
    const int tid = threadIdx.x;
    float* row = g_h + (size_t)b * Mc;

    float mx = -3.402823466e38f;
    for (int m = tid; m < Mc; m += 512) mx = fmaxf(mx, beta * row[m]);
    red[tid] = mx;
    __syncthreads();
    for (int s = 256; s > 0; s >>= 1) {
        if (tid < s) red[tid] = fmaxf(red[tid], red[tid + s]);
        __syncthreads();
    }
    mx = red[0];
    __syncthreads();

    float sum = 0.0f;
    for (int m = tid; m < Mc; m += 512) {
        float e = expf(beta * row[m] - mx);
        row[m] = e;
        sum += e;
    }
    red[tid] = sum;
    __syncthreads();
    for (int s = 256; s > 0; s >>= 1) {
        if (tid < s) red[tid] += red[tid + s];
        __syncthreads();
    }
    const float inv = FSCALE / red[0];
    __syncthreads();

    for (int m = tid; m < Mc; m += 512) {
        float p = row[m] * inv;               // prob * FSCALE
        __half h = __float2half(p);
        g_fhi[(size_t)b * Mc + m] = h;
        g_flo[(size_t)b * Mc + m] = __float2half(p - __half2float(h));
    }
}

// ---------------------------------------------------------------------------
// Persistent kernel: all 50 steps with device-side convergence freeze
// ---------------------------------------------------------------------------
__global__ void __launch_bounds__(512, 1) k_steps(float* __restrict__ state,
                                                  const float* __restrict__ beta_p,
                                                  const float* __restrict__ tau_p,
                                                  int G) {
    extern __shared__ char smem[];
    float* red = (float*)smem;
    const int tid = threadIdx.x;
    const float beta = *beta_p;
    const float invtau = 1.0f / (*tau_p);

    for (int step = 0; step < STEPS; ++step) {
        // GEMM1: h = s . W^T  (256 tiles)
        for (int t = blockIdx.x; t < 256; t += G) gemm_tile<0>(smem, t);
        gbar(G);

        // Softmax rows
        for (int b = blockIdx.x; b < Bc; b += G) softmax_row(b, beta, red);
        gbar(G);

        // GEMM2: v*FSCALE = f_scaled . W (k-split x4)
        for (int t = blockIdx.x; t < 256; t += G) gemm_tile<1>(smem, t);
        gbar(G);

        // Update + norm (undo FSCALE here)
        float sumsq = 0.0f;
        for (int i = blockIdx.x * 512 + tid; i < Bc * Nc; i += G * 512) {
            float v = (g_vpart[0][i] + g_vpart[1][i] +
                       g_vpart[2][i] + g_vpart[3][i]) * INV_FSCALE;
            float so = state[i];
            float nv = so + invtau * (v - so);
            float d = nv - so;
            sumsq += d * d;
            state[i] = nv;
            __half h = __float2half(nv);
            g_shi[i] = h;
            g_slo[i] = __float2half(nv - __half2float(h));
        }
        red[tid] = sumsq;
        __syncthreads();
        for (int s = 256; s > 0; s >>= 1) {
            if (tid < s) red[tid] += red[tid + s];
            __syncthreads();
        }
        if (tid == 0) atomicAdd(&g_norm[step], red[0]);
        gbar(G);

        float nrm = *(volatile float*)&g_norm[step];
        if (sqrtf(nrm) <= 1e-3f) break;
        __syncthreads();
    }
}

// ---------------------------------------------------------------------------
// kernel_launch
// ---------------------------------------------------------------------------
extern "C" void kernel_launch(void* const* d_in, const int* in_sizes, int n_in,
                              void* d_out, int out_size) {
    const float* inp  = (const float*)d_in[0];
    const float* W    = (const float*)d_in[1];
    const float* beta = (const float*)d_in[2];
    const float* tau  = (const float*)d_in[3];
    float* state = (float*)d_out;

    int dev = 0;
    cudaGetDevice(&dev);
    cudaDeviceProp props;
    cudaGetDeviceProperties(&props, dev);
    const int G = props.multiProcessorCount;

    cudaFuncSetAttribute(k_steps, cudaFuncAttributeMaxDynamicSharedMemorySize, SMEM_T);

    k_init<<<(Bc * Nc + 255) / 256, 256>>>(inp, state);
    k_convW<<<dim3(Nc / 32, Mc / 32), dim3(32, 8)>>>(W);
    k_steps<<<G, 512, SMEM_T>>>(state, beta, tau, G);
}

// round 6
// speedup vs baseline: 5.2723x; 1.4086x over previous
#include <cuda_runtime.h>
#include <cuda_bf16.h>
#include <cuda_fp16.h>
#include <cstdint>
#include <math.h>

// Problem dims (fixed by the dataset)
#define Bc 256
#define Nc 4096
#define Mc 16384
#define STEPS 50
#define FSCALE 4096.0f
#define INV_FSCALE (1.0f / 4096.0f)

// ---------------------------------------------------------------------------
// Device-global scratch
// ---------------------------------------------------------------------------
__device__ __half g_Wh [(size_t)Mc * Nc];   // W fp16   [m][n]
__device__ __half g_Wth[(size_t)Nc * Mc];   // W^T fp16 [n][m]
__device__ __half g_sh [(size_t)Bc * Nc];   // state fp16 [b][n] (single - see note)
__device__ __half g_fhi[(size_t)Bc * Mc];   // probs*FSCALE hi [b][m]
__device__ __half g_flo[(size_t)Bc * Mc];   // probs*FSCALE lo
__device__ float  g_h[(size_t)Bc * Mc];     // logits [b][m]
__device__ float  g_vpart[4][(size_t)Bc * Nc];
__device__ float  g_norm[STEPS];

__device__ unsigned g_cnt_bar;
__device__ volatile unsigned g_gen_bar;

// ---------------------------------------------------------------------------
// PTX helpers (sm_80-era, legal on plain sm_103)
// ---------------------------------------------------------------------------
__device__ __forceinline__ uint32_t s2u(const void* p) {
    return (uint32_t)__cvta_generic_to_shared(p);
}
__device__ __forceinline__ void cpa16(uint32_t dst, const void* src) {
    asm volatile("cp.async.cg.shared.global [%0], [%1], 16;" :: "r"(dst), "l"(src));
}
#define CP_COMMIT() asm volatile("cp.async.commit_group;" ::: "memory")
#define CP_WAIT(n)  asm volatile("cp.async.wait_group %0;" :: "n"(n) : "memory")

__device__ __forceinline__ void ldm4(uint32_t* r, uint32_t addr) {
    asm volatile("ldmatrix.sync.aligned.m8n8.x4.shared.b16 {%0,%1,%2,%3}, [%4];"
                 : "=r"(r[0]), "=r"(r[1]), "=r"(r[2]), "=r"(r[3]) : "r"(addr));
}
__device__ __forceinline__ void mma16816(float* d, const uint32_t* a,
                                         uint32_t b0, uint32_t b1) {
    asm volatile(
        "mma.sync.aligned.m16n8k16.row.col.f32.f16.f16.f32 "
        "{%0,%1,%2,%3}, {%4,%5,%6,%7}, {%8,%9}, {%0,%1,%2,%3};"
        : "+f"(d[0]), "+f"(d[1]), "+f"(d[2]), "+f"(d[3])
        : "r"(a[0]), "r"(a[1]), "r"(a[2]), "r"(a[3]), "r"(b0), "r"(b1));
}

// ---------------------------------------------------------------------------
// Software global barrier (grid == #SMs, 1 CTA/SM -> co-resident)
// ---------------------------------------------------------------------------
__device__ __forceinline__ void gbar(int G) {
    __syncthreads();
    if (threadIdx.x == 0) {
        __threadfence();
        unsigned my = g_gen_bar;
        unsigned old = atomicAdd(&g_cnt_bar, 1u);
        if (old == (unsigned)G - 1u) {
            g_cnt_bar = 0u;
            __threadfence();
            g_gen_bar = my + 1u;
        } else {
            while (g_gen_bar == my) __nanosleep(64);
        }
        __threadfence();
    }
    __syncthreads();
}

// ---------------------------------------------------------------------------
// Init
// ---------------------------------------------------------------------------
__global__ void k_init(const float* __restrict__ inp, float* __restrict__ state) {
    int i = blockIdx.x * blockDim.x + threadIdx.x;
    if (i < Bc * Nc) {
        float x = inp[i];
        state[i] = x;
        g_sh[i] = __float2half(x);
    }
    if (i < STEPS) g_norm[i] = 0.0f;
}

// ---------------------------------------------------------------------------
// W -> fp16 + fp16 transpose
// ---------------------------------------------------------------------------
__global__ void __launch_bounds__(256) k_convW(const float* __restrict__ W) {
    __shared__ __half th[32][33];
    const int n0 = blockIdx.x * 32;
    const int m0 = blockIdx.y * 32;
    const int tx = threadIdx.x;
    const int ty = threadIdx.y;
#pragma unroll
    for (int i = 0; i < 4; i++) {
        int r = ty + i * 8;
        size_t gi = (size_t)(m0 + r) * Nc + n0 + tx;
        __half h = __float2half(W[gi]);
        g_Wh[gi] = h;
        th[r][tx] = h;
    }
    __syncthreads();
#pragma unroll
    for (int i = 0; i < 4; i++) {
        int r = ty + i * 8;
        g_Wth[(size_t)(n0 + r) * Mc + m0 + tx] = th[tx][r];
    }
}

// ---------------------------------------------------------------------------
// GEMM tile: 128(b) x 128(c), K=4096, K-chunk 64, 3-stage cp.async,
// ONE __syncthreads per chunk.
// MODE 0: 1 product  (state_h x W)        stage = {A, B}
// MODE 1: 2 products (f_hi/f_lo x W^T)    stage = {Ah, Al, B}
// 16 warps 4(b) x 4(c), 32x32 per warp.
// ---------------------------------------------------------------------------
#define KCH    64
#define NCH    64                  // 4096 / 64
#define ROWB   144                 // 128B data + 16B pad (LDSM conflict-free)
#define TILE_S (128 * ROWB)        // 18432 B
#define NSTG   3
#define SMEM_T (NSTG * 3 * TILE_S) // 165888 B (MODE1 stage = 3 tiles)

__device__ __forceinline__ void load_stage2(
    uint32_t sbase, int tid, const __half* A, const __half* B, size_t ld)
{
#pragma unroll
    for (int t = 0; t < 2; t++) {
        int idx = tid + t * 512;       // 0..1023
        int r = idx >> 3;
        int q = idx & 7;
        uint32_t so = (uint32_t)(r * ROWB + q * 16);
        const size_t go = (size_t)r * ld + q * 8;
        cpa16(sbase + so, A + go);
        cpa16(sbase + TILE_S + so, B + go);
    }
}
__device__ __forceinline__ void load_stage3(
    uint32_t sbase, int tid, const __half* Ah, const __half* Al,
    const __half* B, size_t ld)
{
#pragma unroll
    for (int t = 0; t < 2; t++) {
        int idx = tid + t * 512;
        int r = idx >> 3;
        int q = idx & 7;
        uint32_t so = (uint32_t)(r * ROWB + q * 16);
        const size_t go = (size_t)r * ld + q * 8;
        cpa16(sbase + so, Ah + go);
        cpa16(sbase + TILE_S + so, Al + go);
        cpa16(sbase + 2 * TILE_S + so, B + go);
    }
}

template <int MODE>
__device__ void gemm_tile(char* smem, int t) {
    const int tid = threadIdx.x;
    const int wid = tid >> 5;
    const int lid = tid & 31;
    const int rw  = wid & 3;
    const int cw  = wid >> 2;
    const uint32_t sb = s2u(smem);

    constexpr size_t ld  = MODE ? (size_t)Mc : (size_t)Nc;
    constexpr size_t ldO = MODE ? (size_t)Nc : (size_t)Mc;
    constexpr uint32_t STG = (MODE ? 3u : 2u) * TILE_S;
    constexpr uint32_t BOFF = (MODE ? 2u : 1u) * TILE_S;   // B tile offset in stage

    const int b0 = (t & 1) * 128;
    int c0, z;
    if (MODE) { z = t >> 6; c0 = ((t >> 1) & 31) * 128; }
    else      { z = 0;      c0 = (t >> 1) * 128; }
    const size_t koff = (size_t)z * 4096;

    const __half* Ahp = (MODE ? g_fhi : g_sh) + (size_t)b0 * ld + koff;
    const __half* Alp = g_flo + (size_t)b0 * ld + koff;     // used when MODE==1
    const __half* Bp  = (MODE ? g_Wth : g_Wh) + (size_t)c0 * ld + koff;
    float* out = MODE ? &g_vpart[z][0] : g_h;

    float acc[2][4][4];
#pragma unroll
    for (int i = 0; i < 2; i++)
#pragma unroll
        for (int j = 0; j < 4; j++)
#pragma unroll
            for (int v = 0; v < 4; v++) acc[i][j][v] = 0.0f;

    const int lrow = ((lid >> 3) & 1) * 8 + (lid & 7);
    const int lkb  = (lid >> 4) * 16;

    if (MODE) {
        load_stage3(sb + 0 * STG, tid, Ahp, Alp, Bp, ld);
        CP_COMMIT();
        load_stage3(sb + 1 * STG, tid, Ahp + KCH, Alp + KCH, Bp + KCH, ld);
        CP_COMMIT();
    } else {
        load_stage2(sb + 0 * STG, tid, Ahp, Bp, ld);
        CP_COMMIT();
        load_stage2(sb + 1 * STG, tid, Ahp + KCH, Bp + KCH, ld);
        CP_COMMIT();
    }

    for (int ch = 0; ch < NCH; ++ch) {
        const uint32_t cur = sb + (uint32_t)(ch % NSTG) * STG;
        if (ch + 2 < NCH) {
            CP_WAIT(1);
            __syncthreads();
            const size_t kk = (size_t)(ch + 2) * KCH;
            const uint32_t nst = sb + (uint32_t)((ch + 2) % NSTG) * STG;
            if (MODE) load_stage3(nst, tid, Ahp + kk, Alp + kk, Bp + kk, ld);
            else      load_stage2(nst, tid, Ahp + kk, Bp + kk, ld);
            CP_COMMIT();
        } else {
            CP_WAIT(0);
            __syncthreads();
        }

#pragma unroll
        for (int ks = 0; ks < 4; ++ks) {
            const uint32_t kbyte = (uint32_t)(ks * 32 + lkb);
            uint32_t aF[2][2][4];
            uint32_t bF[2][4];
#pragma unroll
            for (int sub = 0; sub < 2; ++sub) {
                uint32_t ra = (uint32_t)((rw * 32 + sub * 16 + lrow) * ROWB) + kbyte;
                ldm4(aF[0][sub], cur + ra);
                if (MODE) ldm4(aF[1][sub], cur + TILE_S + ra);
            }
#pragma unroll
            for (int cg = 0; cg < 2; ++cg) {
                uint32_t rb = (uint32_t)((cw * 32 + cg * 16 + lrow) * ROWB) + kbyte;
                ldm4(bF[cg], cur + BOFF + rb);
            }
#pragma unroll
            for (int sub = 0; sub < 2; ++sub) {
#pragma unroll
                for (int cg = 0; cg < 2; ++cg) {
#pragma unroll
                    for (int hf = 0; hf < 2; ++hf) {
                        const int nt = cg * 2 + hf;
                        mma16816(acc[sub][nt], aF[0][sub],
                                 bF[cg][hf], bF[cg][hf + 2]);
                        if (MODE)
                            mma16816(acc[sub][nt], aF[1][sub],
                                     bF[cg][hf], bF[cg][hf + 2]);
                    }
                }
            }
        }
        // no trailing sync: with 3 stages, the next overwrite of this stage
        // happens only after the next chunk's mid-sync rate-matches all warps
    }
    __syncthreads();

    const int gr = lid >> 2;
    const int gc = (lid & 3) * 2;
#pragma unroll
    for (int sub = 0; sub < 2; ++sub) {
        const int rbase = b0 + rw * 32 + sub * 16 + gr;
#pragma unroll
        for (int nt = 0; nt < 4; ++nt) {
            const int col = c0 + cw * 32 + nt * 8 + gc;
            float* p0 = out + (size_t)rbase * ldO + col;
            float* p1 = out + (size_t)(rbase + 8) * ldO + col;
            *(float2*)p0 = make_float2(acc[sub][nt][0], acc[sub][nt][1]);
            *(float2*)p1 = make_float2(acc[sub][nt][2], acc[sub][nt][3]);
        }
    }
    __syncthreads();
}

// ---------------------------------------------------------------------------
// Softmax over memory dim for one batch row (512 threads); scaled fp16 split
// ---------------------------------------------------------------------------
__device__ void softmax_row(int b, float beta, float* red) {
    const int tid = threadIdx.x;
    float* row = g_h + (size_t)b * Mc;

    float mx = -3.402823466e38f;
    for (int m = tid; m < Mc; m += 512) mx = fmaxf(mx, beta * row[m]);
    red[tid] = mx;
    __syncthreads();
    for (int s = 256; s > 0; s >>= 1) {
        if (tid < s) red[tid] = fmaxf(red[tid], red[tid + s]);
        __syncthreads();
    }
    mx = red[0];
    __syncthreads();

    float sum = 0.0f;
    for (int m = tid; m < Mc; m += 512) {
        float e = expf(beta * row[m] - mx);
        row[m] = e;
        sum += e;
    }
    red[tid] = sum;
    __syncthreads();
    for (int s = 256; s > 0; s >>= 1) {
        if (tid < s) red[tid] += red[tid + s];
        __syncthreads();
    }
    const float inv = FSCALE / red[0];
    __syncthreads();

    for (int m = tid; m < Mc; m += 512) {
        float p = row[m] * inv;
        __half h = __float2half(p);
        g_fhi[(size_t)b * Mc + m] = h;
        g_flo[(size_t)b * Mc + m] = __float2half(p - __half2float(h));
    }
}

// ---------------------------------------------------------------------------
// Persistent kernel: all steps + device-side convergence freeze
// ---------------------------------------------------------------------------
__global__ void __launch_bounds__(512, 1) k_steps(float* __restrict__ state,
                                                  const float* __restrict__ beta_p,
                                                  const float* __restrict__ tau_p,
                                                  int G) {
    extern __shared__ char smem[];
    float* red = (float*)smem;
    const int tid = threadIdx.x;
    const float beta = *beta_p;
    const float invtau = 1.0f / (*tau_p);

    for (int step = 0; step < STEPS; ++step) {
        for (int t = blockIdx.x; t < 256; t += G) gemm_tile<0>(smem, t);
        gbar(G);

        for (int b = blockIdx.x; b < Bc; b += G) softmax_row(b, beta, red);
        gbar(G);

        for (int t = blockIdx.x; t < 256; t += G) gemm_tile<1>(smem, t);
        gbar(G);

        float sumsq = 0.0f;
        for (int i = blockIdx.x * 512 + tid; i < Bc * Nc; i += G * 512) {
            float v = (g_vpart[0][i] + g_vpart[1][i] +
                       g_vpart[2][i] + g_vpart[3][i]) * INV_FSCALE;
            float so = state[i];
            float nv = so + invtau * (v - so);
            float d = nv - so;
            sumsq += d * d;
            state[i] = nv;
            g_sh[i] = __float2half(nv);
        }
        red[tid] = sumsq;
        __syncthreads();
        for (int s = 256; s > 0; s >>= 1) {
            if (tid < s) red[tid] += red[tid + s];
            __syncthreads();
        }
        if (tid == 0) atomicAdd(&g_norm[step], red[0]);
        gbar(G);

        float nrm = *(volatile float*)&g_norm[step];
        if (sqrtf(nrm) <= 1e-3f) break;
        __syncthreads();
    }
}

// ---------------------------------------------------------------------------
// kernel_launch
// ---------------------------------------------------------------------------
extern "C" void kernel_launch(void* const* d_in, const int* in_sizes, int n_in,
                              void* d_out, int out_size) {
    const float* inp  = (const float*)d_in[0];
    const float* W    = (const float*)d_in[1];
    const float* beta = (const float*)d_in[2];
    const float* tau  = (const float*)d_in[3];
    float* state = (float*)d_out;

    int dev = 0;
    cudaGetDevice(&dev);
    cudaDeviceProp props;
    cudaGetDeviceProperties(&props, dev);
    const int G = props.multiProcessorCount;

    cudaFuncSetAttribute(k_steps, cudaFuncAttributeMaxDynamicSharedMemorySize, SMEM_T);

    k_init<<<(Bc * Nc + 255) / 256, 256>>>(inp, state);
    k_convW<<<dim3(Nc / 32, Mc / 32), dim3(32, 8)>>>(W);
    k_steps<<<G, 512, SMEM_T>>>(state, beta, tau, G);
}

// round 7
// speedup vs baseline: 6.9430x; 1.3169x over previous
#include <cuda_runtime.h>
#include <cuda_bf16.h>
#include <cuda_fp16.h>
#include <cstdint>
#include <math.h>

// Problem dims (fixed by the dataset)
#define Bc 256
#define Nc 4096
#define Mc 16384
#define STEPS 50
#define FSCALE 4096.0f
#define INV_FSCALE (1.0f / 4096.0f)

// ---------------------------------------------------------------------------
// Device-global scratch
// ---------------------------------------------------------------------------
__device__ __half g_Wh [(size_t)Mc * Nc];   // W fp16   [m][n]
__device__ __half g_Wth[(size_t)Nc * Mc];   // W^T fp16 [n][m]
__device__ __half g_sh [(size_t)Bc * Nc];   // state fp16 [b][n]
__device__ __half g_fh [(size_t)Bc * Mc];   // probs*FSCALE fp16 [b][m]
__device__ float  g_h[(size_t)Bc * Mc];     // exp(beta*h) [b][m]
__device__ float  g_fsum[Bc];               // per-row exp sums
__device__ float  g_vpart[4][(size_t)Bc * Nc];
__device__ float  g_norm[STEPS];

__device__ unsigned g_cnt_bar;
__device__ volatile unsigned g_gen_bar;

// ---------------------------------------------------------------------------
// PTX helpers (sm_80-era, legal on plain sm_103)
// ---------------------------------------------------------------------------
__device__ __forceinline__ uint32_t s2u(const void* p) {
    return (uint32_t)__cvta_generic_to_shared(p);
}
__device__ __forceinline__ void cpa16(uint32_t dst, const void* src) {
    asm volatile("cp.async.cg.shared.global [%0], [%1], 16;" :: "r"(dst), "l"(src));
}
#define CP_COMMIT() asm volatile("cp.async.commit_group;" ::: "memory")
#define CP_WAIT(n)  asm volatile("cp.async.wait_group %0;" :: "n"(n) : "memory")

__device__ __forceinline__ void ldm4(uint32_t* r, uint32_t addr) {
    asm volatile("ldmatrix.sync.aligned.m8n8.x4.shared.b16 {%0,%1,%2,%3}, [%4];"
                 : "=r"(r[0]), "=r"(r[1]), "=r"(r[2]), "=r"(r[3]) : "r"(addr));
}
__device__ __forceinline__ void mma16816(float* d, const uint32_t* a,
                                         uint32_t b0, uint32_t b1) {
    asm volatile(
        "mma.sync.aligned.m16n8k16.row.col.f32.f16.f16.f32 "
        "{%0,%1,%2,%3}, {%4,%5,%6,%7}, {%8,%9}, {%0,%1,%2,%3};"
        : "+f"(d[0]), "+f"(d[1]), "+f"(d[2]), "+f"(d[3])
        : "r"(a[0]), "r"(a[1]), "r"(a[2]), "r"(a[3]), "r"(b0), "r"(b1));
}

// ---------------------------------------------------------------------------
// Software global barrier (all CTAs co-resident: grid == #SMs)
// ---------------------------------------------------------------------------
__device__ __forceinline__ void gbar(int G) {
    __syncthreads();
    if (threadIdx.x == 0) {
        __threadfence();
        unsigned my = g_gen_bar;
        unsigned old = atomicAdd(&g_cnt_bar, 1u);
        if (old == (unsigned)G - 1u) {
            g_cnt_bar = 0u;
            __threadfence();
            g_gen_bar = my + 1u;
        } else {
            while (g_gen_bar == my) __nanosleep(64);
        }
        __threadfence();
    }
    __syncthreads();
}

// ---------------------------------------------------------------------------
// Init
// ---------------------------------------------------------------------------
__global__ void k_init(const float* __restrict__ inp, float* __restrict__ state) {
    int i = blockIdx.x * blockDim.x + threadIdx.x;
    if (i < Bc * Nc) {
        float x = inp[i];
        state[i] = x;
        g_sh[i] = __float2half(x);
    }
    if (i < STEPS) g_norm[i] = 0.0f;
    if (i < Bc) g_fsum[i] = 0.0f;
}

// ---------------------------------------------------------------------------
// W -> fp16 + fp16 transpose
// ---------------------------------------------------------------------------
__global__ void __launch_bounds__(256) k_convW(const float* __restrict__ W) {
    __shared__ __half th[32][33];
    const int n0 = blockIdx.x * 32;
    const int m0 = blockIdx.y * 32;
    const int tx = threadIdx.x;
    const int ty = threadIdx.y;
#pragma unroll
    for (int i = 0; i < 4; i++) {
        int r = ty + i * 8;
        size_t gi = (size_t)(m0 + r) * Nc + n0 + tx;
        __half h = __float2half(W[gi]);
        g_Wh[gi] = h;
        th[r][tx] = h;
    }
    __syncthreads();
#pragma unroll
    for (int i = 0; i < 4; i++) {
        int r = ty + i * 8;
        g_Wth[(size_t)(n0 + r) * Mc + m0 + tx] = th[tx][r];
    }
}

// ---------------------------------------------------------------------------
// Unified single-product GEMM tile: C[128(b) x 128(c)] = A[b][k]*B[c][k],
// K=4096, K-chunk 64, 3-stage cp.async, one sync per chunk.
// 16 warps 4(b) x 4(c), 32x32 per warp.
// MODE 0: A=state fp16, B=W    -> epilogue: store exp(beta*acc), row sums
// MODE 1: A=f fp16,     B=W^T  -> plain store to g_vpart[z]
// ---------------------------------------------------------------------------
#define KCH    64
#define NCH    64                  // 4096 / 64
#define ROWB   144                 // 128B data + 16B pad (LDSM conflict-free)
#define TILE_S (128 * ROWB)        // 18432 B
#define NSTG   3
#define STG_S  (2 * TILE_S)        // A + B tiles
#define SMEM_T (NSTG * STG_S)      // 110592 B

__device__ __forceinline__ void load_stage(
    uint32_t sbase, int tid, const __half* A, const __half* B, size_t ld)
{
#pragma unroll
    for (int t = 0; t < 2; t++) {
        int idx = tid + t * 512;       // 0..1023
        int r = idx >> 3;
        int q = idx & 7;
        uint32_t so = (uint32_t)(r * ROWB + q * 16);
        const size_t go = (size_t)r * ld + q * 8;
        cpa16(sbase + so, A + go);
        cpa16(sbase + TILE_S + so, B + go);
    }
}

template <int MODE>
__device__ void gemm_tile(char* smem, int t, float beta) {
    const int tid = threadIdx.x;
    const int wid = tid >> 5;
    const int lid = tid & 31;
    const int rw  = wid & 3;
    const int cw  = wid >> 2;
    const uint32_t sb = s2u(smem);

    constexpr size_t ld  = MODE ? (size_t)Mc : (size_t)Nc;
    constexpr size_t ldO = MODE ? (size_t)Nc : (size_t)Mc;

    const int b0 = (t & 1) * 128;
    int c0, z;
    if (MODE) { z = t >> 6; c0 = ((t >> 1) & 31) * 128; }
    else      { z = 0;      c0 = (t >> 1) * 128; }
    const size_t koff = (size_t)z * 4096;

    const __half* Ap = (MODE ? g_fh : g_sh) + (size_t)b0 * ld + koff;
    const __half* Bp = (MODE ? g_Wth : g_Wh) + (size_t)c0 * ld + koff;
    float* out = MODE ? &g_vpart[z][0] : g_h;

    float acc[2][4][4];
#pragma unroll
    for (int i = 0; i < 2; i++)
#pragma unroll
        for (int j = 0; j < 4; j++)
#pragma unroll
            for (int v = 0; v < 4; v++) acc[i][j][v] = 0.0f;

    const int lrow = ((lid >> 3) & 1) * 8 + (lid & 7);
    const int lkb  = (lid >> 4) * 16;

    load_stage(sb + 0 * STG_S, tid, Ap, Bp, ld);
    CP_COMMIT();
    load_stage(sb + 1 * STG_S, tid, Ap + KCH, Bp + KCH, ld);
    CP_COMMIT();

    for (int ch = 0; ch < NCH; ++ch) {
        const uint32_t cur = sb + (uint32_t)(ch % NSTG) * STG_S;
        if (ch + 2 < NCH) {
            CP_WAIT(1);
            __syncthreads();
            const size_t kk = (size_t)(ch + 2) * KCH;
            load_stage(sb + (uint32_t)((ch + 2) % NSTG) * STG_S, tid,
                       Ap + kk, Bp + kk, ld);
            CP_COMMIT();
        } else {
            CP_WAIT(0);
            __syncthreads();
        }

#pragma unroll
        for (int ks = 0; ks < 4; ++ks) {
            const uint32_t kbyte = (uint32_t)(ks * 32 + lkb);
            uint32_t aF[2][4];
            uint32_t bF[2][4];
#pragma unroll
            for (int sub = 0; sub < 2; ++sub) {
                uint32_t ra = (uint32_t)((rw * 32 + sub * 16 + lrow) * ROWB) + kbyte;
                ldm4(aF[sub], cur + ra);
            }
#pragma unroll
            for (int cg = 0; cg < 2; ++cg) {
                uint32_t rb = (uint32_t)((cw * 32 + cg * 16 + lrow) * ROWB) + kbyte;
                ldm4(bF[cg], cur + TILE_S + rb);
            }
#pragma unroll
            for (int sub = 0; sub < 2; ++sub)
#pragma unroll
                for (int cg = 0; cg < 2; ++cg)
#pragma unroll
                    for (int hf = 0; hf < 2; ++hf)
                        mma16816(acc[sub][cg * 2 + hf], aF[sub],
                                 bF[cg][hf], bF[cg][hf + 2]);
        }
    }
    __syncthreads();   // stages dead after this; smem reusable in epilogue

    const int gr = lid >> 2;
    const int gc = (lid & 3) * 2;

    if (MODE == 0) {
        // Epilogue: e = exp(beta*h); store e; reduce row sums
        float* rsum = (float*)smem;
        if (tid < 128) rsum[tid] = 0.0f;
        __syncthreads();

#pragma unroll
        for (int sub = 0; sub < 2; ++sub) {
            const int rbase = b0 + rw * 32 + sub * 16 + gr;
            float s0 = 0.0f, s1 = 0.0f;
#pragma unroll
            for (int nt = 0; nt < 4; ++nt) {
                float e0 = expf(beta * acc[sub][nt][0]);
                float e1 = expf(beta * acc[sub][nt][1]);
                float e2 = expf(beta * acc[sub][nt][2]);
                float e3 = expf(beta * acc[sub][nt][3]);
                const int col = c0 + cw * 32 + nt * 8 + gc;
                *(float2*)(out + (size_t)rbase * ldO + col) = make_float2(e0, e1);
                *(float2*)(out + (size_t)(rbase + 8) * ldO + col) = make_float2(e2, e3);
                s0 += e0 + e1;
                s1 += e2 + e3;
            }
            // reduce across the 4 lanes sharing this row (lid&3)
            s0 += __shfl_xor_sync(0xFFFFFFFF, s0, 1);
            s0 += __shfl_xor_sync(0xFFFFFFFF, s0, 2);
            s1 += __shfl_xor_sync(0xFFFFFFFF, s1, 1);
            s1 += __shfl_xor_sync(0xFFFFFFFF, s1, 2);
            if ((lid & 3) == 0) {
                atomicAdd(&rsum[rw * 32 + sub * 16 + gr], s0);
                atomicAdd(&rsum[rw * 32 + sub * 16 + gr + 8], s1);
            }
        }
        __syncthreads();
        if (tid < 128) atomicAdd(&g_fsum[b0 + tid], rsum[tid]);
        __syncthreads();
    } else {
#pragma unroll
        for (int sub = 0; sub < 2; ++sub) {
            const int rbase = b0 + rw * 32 + sub * 16 + gr;
#pragma unroll
            for (int nt = 0; nt < 4; ++nt) {
                const int col = c0 + cw * 32 + nt * 8 + gc;
                *(float2*)(out + (size_t)rbase * ldO + col) =
                    make_float2(acc[sub][nt][0], acc[sub][nt][1]);
                *(float2*)(out + (size_t)(rbase + 8) * ldO + col) =
                    make_float2(acc[sub][nt][2], acc[sub][nt][3]);
            }
        }
        __syncthreads();
    }
}

// ---------------------------------------------------------------------------
// Normalize pass: f = e / sum, scaled, fp16 store
// ---------------------------------------------------------------------------
__device__ void normalize_row(int b) {
    const int tid = threadIdx.x;
    const float inv = FSCALE / g_fsum[b];
    const float* row = g_h + (size_t)b * Mc;
    __half* dst = g_fh + (size_t)b * Mc;
    for (int m = tid; m < Mc; m += 512)
        dst[m] = __float2half(row[m] * inv);
}

// ---------------------------------------------------------------------------
// Persistent kernel: all steps + device-side convergence freeze
// ---------------------------------------------------------------------------
__global__ void __launch_bounds__(512, 1) k_steps(float* __restrict__ state,
                                                  const float* __restrict__ beta_p,
                                                  const float* __restrict__ tau_p,
                                                  int G) {
    extern __shared__ char smem[];
    float* red = (float*)smem;
    const int tid = threadIdx.x;
    const float beta = *beta_p;
    const float invtau = 1.0f / (*tau_p);

    for (int step = 0; step < STEPS; ++step) {
        // GEMM1 + fused exp/rowsum
        for (int t = blockIdx.x; t < 256; t += G) gemm_tile<0>(smem, t, beta);
        gbar(G);

        // Normalize probs -> fp16
        for (int b = blockIdx.x; b < Bc; b += G) normalize_row(b);
        gbar(G);

        // GEMM2 (k-split x4); CTA 0 re-zeros g_fsum for the next step
        if (blockIdx.x == 0 && tid < Bc) g_fsum[tid] = 0.0f;
        for (int t = blockIdx.x; t < 256; t += G) gemm_tile<1>(smem, t, beta);
        gbar(G);

        // Update + norm
        float sumsq = 0.0f;
        for (int i = blockIdx.x * 512 + tid; i < Bc * Nc; i += G * 512) {
            float v = (g_vpart[0][i] + g_vpart[1][i] +
                       g_vpart[2][i] + g_vpart[3][i]) * INV_FSCALE;
            float so = state[i];
            float nv = so + invtau * (v - so);
            float d = nv - so;
            sumsq += d * d;
            state[i] = nv;
            g_sh[i] = __float2half(nv);
        }
        red[tid] = sumsq;
        __syncthreads();
        for (int s = 256; s > 0; s >>= 1) {
            if (tid < s) red[tid] += red[tid + s];
            __syncthreads();
        }
        if (tid == 0) atomicAdd(&g_norm[step], red[0]);
        gbar(G);

        float nrm = *(volatile float*)&g_norm[step];
        if (sqrtf(nrm) <= 1e-3f) break;
        __syncthreads();
    }
}

// ---------------------------------------------------------------------------
// kernel_launch
// ---------------------------------------------------------------------------
extern "C" void kernel_launch(void* const* d_in, const int* in_sizes, int n_in,
                              void* d_out, int out_size) {
    const float* inp  = (const float*)d_in[0];
    const float* W    = (const float*)d_in[1];
    const float* beta = (const float*)d_in[2];
    const float* tau  = (const float*)d_in[3];
    float* state = (float*)d_out;

    int dev = 0;
    cudaGetDevice(&dev);
    cudaDeviceProp props;
    cudaGetDeviceProperties(&props, dev);
    const int G = props.multiProcessorCount;

    cudaFuncSetAttribute(k_steps, cudaFuncAttributeMaxDynamicSharedMemorySize, SMEM_T);

    k_init<<<(Bc * Nc + 255) / 256, 256>>>(inp, state);
    k_convW<<<dim3(Nc / 32, Mc / 32), dim3(32, 8)>>>(W);
    k_steps<<<G, 512, SMEM_T>>>(state, beta, tau, G);
}

// round 8
// speedup vs baseline: 8.0190x; 1.1550x over previous
#include <cuda_runtime.h>
#include <cuda_bf16.h>
#include <cuda_fp16.h>
#include <cstdint>
#include <math.h>

// Problem dims (fixed by the dataset)
#define Bc 256
#define Nc 4096
#define Mc 16384
#define STEPS 50

// ---------------------------------------------------------------------------
// Device-global scratch
// ---------------------------------------------------------------------------
__device__ __half g_Wh [(size_t)Mc * Nc];   // W fp16 [m][n] (used by BOTH GEMMs)
__device__ __half g_sh [(size_t)Bc * Nc];   // state fp16 [b][n]
__device__ __half g_fh [(size_t)Bc * Mc];   // e = exp(beta*h) fp16 [b][m]
__device__ float  g_fsum [Bc];              // per-row exp sums (accumulating)
__device__ float  g_fsum2[Bc];              // snapshot read by update
__device__ float  g_vpart[2][(size_t)Bc * Nc];
__device__ float  g_norm[STEPS];

__device__ unsigned g_cnt_bar;
__device__ volatile unsigned g_gen_bar;

// ---------------------------------------------------------------------------
// PTX helpers (sm_80-era, legal on plain sm_103)
// ---------------------------------------------------------------------------
__device__ __forceinline__ uint32_t s2u(const void* p) {
    return (uint32_t)__cvta_generic_to_shared(p);
}
__device__ __forceinline__ void cpa16(uint32_t dst, const void* src) {
    asm volatile("cp.async.cg.shared.global [%0], [%1], 16;" :: "r"(dst), "l"(src));
}
#define CP_COMMIT() asm volatile("cp.async.commit_group;" ::: "memory")
#define CP_WAIT(n)  asm volatile("cp.async.wait_group %0;" :: "n"(n) : "memory")

__device__ __forceinline__ void ldm4(uint32_t* r, uint32_t addr) {
    asm volatile("ldmatrix.sync.aligned.m8n8.x4.shared.b16 {%0,%1,%2,%3}, [%4];"
                 : "=r"(r[0]), "=r"(r[1]), "=r"(r[2]), "=r"(r[3]) : "r"(addr));
}
__device__ __forceinline__ void ldm4t(uint32_t* r, uint32_t addr) {
    asm volatile("ldmatrix.sync.aligned.m8n8.x4.trans.shared.b16 {%0,%1,%2,%3}, [%4];"
                 : "=r"(r[0]), "=r"(r[1]), "=r"(r[2]), "=r"(r[3]) : "r"(addr));
}
__device__ __forceinline__ void mma16816(float* d, const uint32_t* a,
                                         uint32_t b0, uint32_t b1) {
    asm volatile(
        "mma.sync.aligned.m16n8k16.row.col.f32.f16.f16.f32 "
        "{%0,%1,%2,%3}, {%4,%5,%6,%7}, {%8,%9}, {%0,%1,%2,%3};"
        : "+f"(d[0]), "+f"(d[1]), "+f"(d[2]), "+f"(d[3])
        : "r"(a[0]), "r"(a[1]), "r"(a[2]), "r"(a[3]), "r"(b0), "r"(b1));
}

// ---------------------------------------------------------------------------
// Software global barrier (all CTAs co-resident: grid == #SMs)
// ---------------------------------------------------------------------------
__device__ __forceinline__ void gbar(int G) {
    __syncthreads();
    if (threadIdx.x == 0) {
        __threadfence();
        unsigned my = g_gen_bar;
        unsigned old = atomicAdd(&g_cnt_bar, 1u);
        if (old == (unsigned)G - 1u) {
            g_cnt_bar = 0u;
            __threadfence();
            g_gen_bar = my + 1u;
        } else {
            while (g_gen_bar == my) __nanosleep(64);
        }
        __threadfence();
    }
    __syncthreads();
}

// ---------------------------------------------------------------------------
// Init
// ---------------------------------------------------------------------------
__global__ void k_init(const float* __restrict__ inp, float* __restrict__ state) {
    int i = blockIdx.x * blockDim.x + threadIdx.x;
    if (i < Bc * Nc) {
        float x = inp[i];
        state[i] = x;
        g_sh[i] = __float2half(x);
    }
    if (i < STEPS) g_norm[i] = 0.0f;
    if (i < Bc) { g_fsum[i] = 0.0f; g_fsum2[i] = 0.0f; }
}

// ---------------------------------------------------------------------------
// W -> fp16 (pure elementwise; no transpose needed anymore)
// ---------------------------------------------------------------------------
__global__ void __launch_bounds__(256) k_convW(const float* __restrict__ W) {
    size_t i = (size_t)blockIdx.x * 1024 + threadIdx.x * 4;
    float4 v = *(const float4*)(W + i);
    __half2 h0 = __floats2half2_rn(v.x, v.y);
    __half2 h1 = __floats2half2_rn(v.z, v.w);
    *(__half2*)(g_Wh + i) = h0;
    *(__half2*)(g_Wh + i + 2) = h1;
}

// ---------------------------------------------------------------------------
// Single-product fp16 GEMM tile, C[128(b) x 128(c)] = A[b][k] * B[.][.]:
// MODE 0: B = W[c][k] row-major (c=m, k=n), non-trans ldmatrix.
//         Epilogue: e = exp(beta*acc) -> fp16 g_fh, row-sum atomics.
// MODE 1: B = W[k][n] row-major (k=m, n-col), ldmatrix.trans, K=8192 (z-split 2).
//         Epilogue: plain fp32 store to g_vpart[z].
// K-chunk 64, 3-stage cp.async, one sync per chunk, 16 warps 4x4, 32x32/warp.
// ---------------------------------------------------------------------------
#define KCH    64
#define ROWB   144                 // A-tile row stride: 128B data + 16B pad
#define ATILE  (128 * ROWB)        // 18432 B
#define STG_S  (2 * ATILE)         // uniform stage size (36864 B)
#define NSTG   3
#define SMEM_T (NSTG * STG_S)      // 110592 B

template <int MODE>
__device__ __forceinline__ void load_stage(
    uint32_t sbase, int tid, const __half* A, const __half* B, int ch)
{
    constexpr size_t ldA = MODE ? (size_t)Mc : (size_t)Nc;
#pragma unroll
    for (int t = 0; t < 2; t++) {
        int idx = tid + t * 512;       // 0..1023
        {   // A tile: 128 rows x 8 segs of 16B
            int r = idx >> 3, q = idx & 7;
            cpa16(sbase + (uint32_t)(r * ROWB + q * 16),
                  A + (size_t)r * ldA + (size_t)ch * KCH + q * 8);
        }
        if (MODE) {
            // B tile: 64 k-rows x 16 segs (256B row), XOR swizzle
            int r = idx >> 4, q = idx & 15;
            cpa16(sbase + ATILE + (uint32_t)(r * 256 + ((q ^ (r & 7)) * 16)),
                  B + ((size_t)ch * KCH + r) * Nc + q * 8);
        } else {
            // B tile: 128 c-rows x 8 segs (K-major, same as A)
            int r = idx >> 3, q = idx & 7;
            cpa16(sbase + ATILE + (uint32_t)(r * ROWB + q * 16),
                  B + (size_t)r * Nc + (size_t)ch * KCH + q * 8);
        }
    }
}

template <int MODE>
__device__ void gemm_tile(char* smem, int t, float beta) {
    const int tid = threadIdx.x;
    const int wid = tid >> 5;
    const int lid = tid & 31;
    const int rw  = wid & 3;
    const int cw  = wid >> 2;
    const uint32_t sb = s2u(smem);

    constexpr size_t ldO = MODE ? (size_t)Nc : (size_t)Mc;
    constexpr int NCH = MODE ? 128 : 64;   // K = 8192 / 4096

    const int b0 = (t & 1) * 128;
    int c0, z;
    if (MODE) { z = t >> 6; c0 = ((t >> 1) & 31) * 128; }
    else      { z = 0;      c0 = (t >> 1) * 128; }
    const size_t koff = (size_t)z * 8192;

    const __half* Ap = MODE ? (g_fh + (size_t)b0 * Mc + koff)
                            : (g_sh + (size_t)b0 * Nc);
    const __half* Bp = MODE ? (g_Wh + koff * Nc + c0)
                            : (g_Wh + (size_t)c0 * Nc);
    float* out = MODE ? &g_vpart[z][0] : (float*)nullptr;

    float acc[2][4][4];
#pragma unroll
    for (int i = 0; i < 2; i++)
#pragma unroll
        for (int j = 0; j < 4; j++)
#pragma unroll
            for (int v = 0; v < 4; v++) acc[i][j][v] = 0.0f;

    const int lrow = ((lid >> 3) & 1) * 8 + (lid & 7);
    const int lkb  = (lid >> 4) * 16;
    const int kr   = ((lid >> 4) & 1) * 8 + (lid & 7);   // trans-load k row
    const int nso  = (lid >> 3) & 1;                     // trans-load nseg offset

    load_stage<MODE>(sb + 0 * STG_S, tid, Ap, Bp, 0);
    CP_COMMIT();
    load_stage<MODE>(sb + 1 * STG_S, tid, Ap, Bp, 1);
    CP_COMMIT();

    for (int ch = 0; ch < NCH; ++ch) {
        const uint32_t cur = sb + (uint32_t)(ch % NSTG) * STG_S;
        if (ch + 2 < NCH) {
            CP_WAIT(1);
            __syncthreads();
            load_stage<MODE>(sb + (uint32_t)((ch + 2) % NSTG) * STG_S, tid,
                             Ap, Bp, ch + 2);
            CP_COMMIT();
        } else {
            CP_WAIT(0);
            __syncthreads();
        }

#pragma unroll
        for (int ks = 0; ks < 4; ++ks) {
            uint32_t aF[2][4];
            uint32_t bF[2][4];
#pragma unroll
            for (int sub = 0; sub < 2; ++sub) {
                uint32_t ra = (uint32_t)((rw * 32 + sub * 16 + lrow) * ROWB
                                         + ks * 32 + lkb);
                ldm4(aF[sub], cur + ra);
            }
#pragma unroll
            for (int cg = 0; cg < 2; ++cg) {
                if (MODE) {
                    const int nseg = cw * 4 + cg * 2 + nso;
                    uint32_t rb = (uint32_t)((ks * 16 + kr) * 256
                                             + ((nseg ^ (lid & 7)) * 16));
                    ldm4t(bF[cg], cur + ATILE + rb);
                } else {
                    uint32_t rb = (uint32_t)((cw * 32 + cg * 16 + lrow) * ROWB
                                             + ks * 32 + lkb);
                    ldm4(bF[cg], cur + ATILE + rb);
                }
            }
#pragma unroll
            for (int sub = 0; sub < 2; ++sub)
#pragma unroll
                for (int cg = 0; cg < 2; ++cg)
#pragma unroll
                    for (int hf = 0; hf < 2; ++hf)
                        mma16816(acc[sub][cg * 2 + hf], aF[sub],
                                 bF[cg][hf], bF[cg][hf + 2]);
        }
    }
    __syncthreads();   // stages dead; smem reusable in epilogue

    const int gr = lid >> 2;
    const int gc = (lid & 3) * 2;

    if (MODE == 0) {
        // Epilogue: e = exp(beta*h) -> fp16 g_fh; row-sum reduction
        float* rsum = (float*)smem;
        if (tid < 128) rsum[tid] = 0.0f;
        __syncthreads();

#pragma unroll
        for (int sub = 0; sub < 2; ++sub) {
            const int rbase = b0 + rw * 32 + sub * 16 + gr;
            float s0 = 0.0f, s1 = 0.0f;
#pragma unroll
            for (int nt = 0; nt < 4; ++nt) {
                float e0 = expf(beta * acc[sub][nt][0]);
                float e1 = expf(beta * acc[sub][nt][1]);
                float e2 = expf(beta * acc[sub][nt][2]);
                float e3 = expf(beta * acc[sub][nt][3]);
                const int col = c0 + cw * 32 + nt * 8 + gc;
                *(__half2*)(g_fh + (size_t)rbase * Mc + col) =
                    __floats2half2_rn(e0, e1);
                *(__half2*)(g_fh + (size_t)(rbase + 8) * Mc + col) =
                    __floats2half2_rn(e2, e3);
                s0 += e0 + e1;
                s1 += e2 + e3;
            }
            s0 += __shfl_xor_sync(0xFFFFFFFF, s0, 1);
            s0 += __shfl_xor_sync(0xFFFFFFFF, s0, 2);
            s1 += __shfl_xor_sync(0xFFFFFFFF, s1, 1);
            s1 += __shfl_xor_sync(0xFFFFFFFF, s1, 2);
            if ((lid & 3) == 0) {
                atomicAdd(&rsum[rw * 32 + sub * 16 + gr], s0);
                atomicAdd(&rsum[rw * 32 + sub * 16 + gr + 8], s1);
            }
        }
        __syncthreads();
        if (tid < 128) atomicAdd(&g_fsum[b0 + tid], rsum[tid]);
        __syncthreads();
    } else {
#pragma unroll
        for (int sub = 0; sub < 2; ++sub) {
            const int rbase = b0 + rw * 32 + sub * 16 + gr;
#pragma unroll
            for (int nt = 0; nt < 4; ++nt) {
                const int col = c0 + cw * 32 + nt * 8 + gc;
                *(float2*)(out + (size_t)rbase * ldO + col) =
                    make_float2(acc[sub][nt][0], acc[sub][nt][1]);
                *(float2*)(out + (size_t)(rbase + 8) * ldO + col) =
                    make_float2(acc[sub][nt][2], acc[sub][nt][3]);
            }
        }
        __syncthreads();
    }
}

// ---------------------------------------------------------------------------
// Persistent kernel: all steps + device-side convergence freeze
// ---------------------------------------------------------------------------
__global__ void __launch_bounds__(512, 1) k_steps(float* __restrict__ state,
                                                  const float* __restrict__ beta_p,
                                                  const float* __restrict__ tau_p,
                                                  int G) {
    extern __shared__ char smem[];
    float* red = (float*)smem;
    const int tid = threadIdx.x;
    const float beta = *beta_p;
    const float invtau = 1.0f / (*tau_p);

    for (int step = 0; step < STEPS; ++step) {
        // GEMM1 + fused exp/rowsum (256 tiles)
        for (int t = blockIdx.x; t < 256; t += G) gemm_tile<0>(smem, t, beta);
        gbar(G);

        // GEMM2 on unnormalized e (128 tiles, z-split 2).
        // CTA 0 snapshots + re-zeros the row sums for the next step.
        if (blockIdx.x == 0 && tid < Bc) {
            g_fsum2[tid] = g_fsum[tid];
            g_fsum[tid] = 0.0f;
        }
        for (int t = blockIdx.x; t < 128; t += G) gemm_tile<1>(smem, t, beta);
        gbar(G);

        // Update + norm (normalization deferred to here: v = u / sum)
        float sumsq = 0.0f;
        for (int i = blockIdx.x * 512 + tid; i < Bc * Nc; i += G * 512) {
            int b = i >> 12;                       // Nc = 4096
            float v = (g_vpart[0][i] + g_vpart[1][i]) / g_fsum2[b];
            float so = state[i];
            float nv = so + invtau * (v - so);
            float d = nv - so;
            sumsq += d * d;
            state[i] = nv;
            g_sh[i] = __float2half(nv);
        }
        red[tid] = sumsq;
        __syncthreads();
        for (int s = 256; s > 0; s >>= 1) {
            if (tid < s) red[tid] += red[tid + s];
            __syncthreads();
        }
        if (tid == 0) atomicAdd(&g_norm[step], red[0]);
        gbar(G);

        float nrm = *(volatile float*)&g_norm[step];
        if (sqrtf(nrm) <= 1e-3f) break;
        __syncthreads();
    }
}

// ---------------------------------------------------------------------------
// kernel_launch
// ---------------------------------------------------------------------------
extern "C" void kernel_launch(void* const* d_in, const int* in_sizes, int n_in,
                              void* d_out, int out_size) {
    const float* inp  = (const float*)d_in[0];
    const float* W    = (const float*)d_in[1];
    const float* beta = (const float*)d_in[2];
    const float* tau  = (const float*)d_in[3];
    float* state = (float*)d_out;

    int dev = 0;
    cudaGetDevice(&dev);
    cudaDeviceProp props;
    cudaGetDeviceProperties(&props, dev);
    const int G = props.multiProcessorCount;

    cudaFuncSetAttribute(k_steps, cudaFuncAttributeMaxDynamicSharedMemorySize, SMEM_T);

    k_init<<<(Bc * Nc + 255) / 256, 256>>>(inp, state);
    k_convW<<<(size_t)Mc * Nc / 1024, 256>>>(W);
    k_steps<<<G, 512, SMEM_T>>>(state, beta, tau, G);
}